// round 14
// baseline (speedup 1.0000x reference)
#include <cuda_runtime.h>
#include <cuda_fp16.h>
#include <cstdint>

#define NA 8
#define NB 16384
#define NS 456
#define NACT 16
#define NIDIM 472
#define NH 256
#define NE 4
#define ND 64

#define KP_IN  480
#define KP_H   256
#define KP_C   512

// ---------------- scratch (device globals) ----------------------------------
__device__ __half g_sa_h [(size_t)NA * NB * NH];
__device__ __half g_sa_l [(size_t)NA * NB * NH];
__device__ __half g_ci_h [(size_t)NA * NB * KP_C];   // [s_enc | other]
__device__ __half g_ci_l [(size_t)NA * NB * KP_C];
__device__ float g_keys[(size_t)NA * NB * NH];
__device__ float g_vals[(size_t)NA * NB * NH];
__device__ float g_sels[(size_t)NA * NB * NH];
__device__ float g_h   [(size_t)NA * NB * NH];
// fused enc|s weights: [A][512][480]
__device__ __half g_wES_h[(size_t)NA * 512 * KP_IN];
__device__ __half g_wES_l[(size_t)NA * 512 * KP_IN];
__device__ __half g_wC_h [(size_t)NA * 256 * KP_C];
__device__ __half g_wC_l [(size_t)NA * 256 * KP_C];
__device__ __half g_wKV_h[(size_t)512 * 256];        // [keys | vals]
__device__ __half g_wKV_l[(size_t)512 * 256];
__device__ __half g_wQ_h [(size_t)256 * 256];
__device__ __half g_wQ_l [(size_t)256 * 256];
__device__ float g_bias_kv[512];
__device__ float g_bias_es[(size_t)NA * 512];        // [enc_b | s_b]

// ---------------- helpers ----------------------------------------------------
__device__ __forceinline__ uint32_t s2u(const void* p) {
    uint32_t a;
    asm("{ .reg .u64 t; cvta.to.shared.u64 t, %1; cvt.u32.u64 %0, t; }"
        : "=r"(a) : "l"(p));
    return a;
}
#define CPA16(d, s) \
    asm volatile("cp.async.cg.shared.global [%0], [%1], 16;" :: "r"(d), "l"(s))
#define CPC()  asm volatile("cp.async.commit_group;")
#define CPW2() asm volatile("cp.async.wait_group 2;")
#define LDSM4(R0, R1, R2, R3, A) \
    asm volatile("ldmatrix.sync.aligned.m8n8.x4.shared.b16 {%0,%1,%2,%3}, [%4];" \
        : "=r"(R0), "=r"(R1), "=r"(R2), "=r"(R3) : "r"(A))

__device__ __forceinline__ void split_h(float x, __half& hi, __half& lo) {
    hi = __float2half_rn(x);
    lo = __float2half_rn(x - __half2float(hi));
}

#define MMA_F16(d, a, b0, b1) \
    asm volatile("mma.sync.aligned.m16n8k16.row.col.f32.f16.f16.f32 " \
        "{%0,%1,%2,%3}, {%4,%5,%6,%7}, {%8,%9}, {%0,%1,%2,%3};" \
        : "+f"((d)[0]), "+f"((d)[1]), "+f"((d)[2]), "+f"((d)[3]) \
        : "r"((a)[0]), "r"((a)[1]), "r"((a)[2]), "r"((a)[3]), "r"(b0), "r"(b1))

// ---------------- weight prep (one kernel) -----------------------------------
#define SEG_ES  0L
#define SEG_C   1966080L
#define SEG_K   3014656L
#define SEG_V   3080192L
#define SEG_Q   3145728L
#define SEG_BKV 3211264L
#define SEG_BES 3211776L
#define SEG_END 3215872L

__device__ __forceinline__ void hsplit(const float* W, __half* wh, __half* wl, long j)
{
    int k = (int)(j & 255);
    int n = (int)(j >> 8);
    float v = W[((long)(n >> 6) * 256 + k) * 64 + (n & 63)];
    __half h, l; split_h(v, h, l);
    wh[(long)n * 256 + k] = h;
    wl[(long)n * 256 + k] = l;
}

__global__ void prep_all(const float* __restrict__ enc_W, const float* __restrict__ s_W,
                         const float* __restrict__ c_W1, const float* __restrict__ key_W,
                         const float* __restrict__ val_W, const float* __restrict__ sel_W,
                         const float* __restrict__ val_b, const float* __restrict__ enc_b,
                         const float* __restrict__ s_b,
                         __half* wESh, __half* wESl, __half* wCh, __half* wCl,
                         __half* wKVh, __half* wKVl, __half* wQh, __half* wQl,
                         float* bkv, float* bes)
{
    long i = (long)blockIdx.x * 256 + threadIdx.x;
    if (i >= SEG_END) return;
    if (i < SEG_C) {
        long j = i;
        int kp = (int)(j % KP_IN);
        int n  = (int)((j / KP_IN) & 511);
        int a  = (int)(j / ((long)KP_IN * 512));
        float v = 0.f;
        if (n < 256) { if (kp < NIDIM) v = enc_W[((long)a * NIDIM + kp) * 256 + n]; }
        else         { if (kp < NS)    v = s_W[((long)a * NS + kp) * 256 + (n - 256)]; }
        __half h, l; split_h(v, h, l);
        wESh[j] = h; wESl[j] = l;
    } else if (i < SEG_K) {
        long j = i - SEG_C;
        int kp = (int)(j % KP_C);
        int n  = (int)((j / KP_C) & 255);
        int a  = (int)(j / ((long)KP_C * 256));
        float v = c_W1[((long)a * KP_C + kp) * 256 + n];
        __half h, l; split_h(v, h, l);
        wCh[j] = h; wCl[j] = l;
    }
    else if (i < SEG_V)   hsplit(key_W, wKVh, wKVl, i - SEG_K);
    else if (i < SEG_Q)   hsplit(val_W, wKVh + 65536, wKVl + 65536, i - SEG_V);
    else if (i < SEG_BKV) hsplit(sel_W, wQh, wQl, i - SEG_Q);
    else if (i < SEG_BES) {
        int j = (int)(i - SEG_BKV);
        bkv[j] = (j < 256) ? 0.f : val_b[j - 256];
    } else {
        int j = (int)(i - SEG_BES);     // a*512 + n
        int a = j >> 9;
        int n = j & 511;
        bes[j] = (n < 256) ? enc_b[a * 256 + n] : s_b[a * 256 + (n - 256)];
    }
}

// ---------------- shared GEMM plumbing: 4-stage x 16-K pipeline --------------
#define TS 24                          // smem row stride in halves (48B)
#define BUFB (128 * TS * 2)            // 6144 B per tensor tile
#define STG  (4 * BUFB)                // 24576 B per stage (AH,AL,BH,BL)
#define SMEM_TOT (4 * STG)             // 98304

// ---------------- ES GEMM: direct fp32 A (states|actions), half-pair out ----
__global__ __launch_bounds__(256, 2)
void gemmES(const float* __restrict__ st, const float* __restrict__ ac,
            const __half* __restrict__ Bh, const __half* __restrict__ Bl,
            const float* __restrict__ bes,
            __half* __restrict__ sah, __half* __restrict__ sal,
            __half* __restrict__ cih, __half* __restrict__ cil)
{
    extern __shared__ char smem[];
    const uint32_t sb = s2u(smem);

    const int a = blockIdx.z;
    const int tid = threadIdx.x;
    const int lane = tid & 31;
    const int wid = tid >> 5;
    const int wm = wid & 3;
    const int wn = wid >> 2;
    const int lr = lane >> 2;
    const int lc = lane & 3;
    const int rowBase = blockIdx.y * 128;
    const int colBase = blockIdx.x * 128;

    // per-thread load mapping: row = tid>>1 (0..127), 8 elems at (tid&1)*8
    const int arow = tid >> 1;
    const int c8   = tid & 1;
    const float* strow = st + ((long)a * NB + rowBase + arow) * NS;
    const float* acrow = ac + ((long)a * NB + rowBase + arow) * NACT;
    const uint32_t dstBase = (uint32_t)(arow * (TS * 2) + c8 * 16);

    const __half* pBh = Bh + (long)a * (512L * KP_IN) + (long)colBase * KP_IN;
    const __half* pBl = Bl + (long)a * (512L * KP_IN) + (long)colBase * KP_IN;

    float acc[2][8][4];
#pragma unroll
    for (int mt = 0; mt < 2; mt++)
#pragma unroll
        for (int nt = 0; nt < 8; nt++)
#pragma unroll
            for (int j = 0; j < 4; j++) acc[mt][nt][j] = 0.f;

    auto loadA8 = [&](float4* v, int kc) {
#pragma unroll
        for (int q = 0; q < 2; q++) {
            const int k = kc + c8 * 8 + q * 4;
            if (k < NS)          v[q] = *(const float4*)(strow + k);
            else if (k < NIDIM)  v[q] = *(const float4*)(acrow + (k - NS));
            else                 v[q] = make_float4(0.f, 0.f, 0.f, 0.f);
        }
    };
    auto storeA = [&](const float4* v, int s) {
        const uint32_t base = sb + (uint32_t)((s & 3) * STG) + dstBase;
        uint32_t h[4], l[4];
#pragma unroll
        for (int q = 0; q < 2; q++) {
            __half h0, l0, h1, l1, h2, l2, h3, l3;
            split_h(v[q].x, h0, l0); split_h(v[q].y, h1, l1);
            split_h(v[q].z, h2, l2); split_h(v[q].w, h3, l3);
            __half2 hh0 = __halves2half2(h0, h1), hh1 = __halves2half2(h2, h3);
            __half2 ll0 = __halves2half2(l0, l1), ll1 = __halves2half2(l2, l3);
            h[q * 2]     = *(uint32_t*)&hh0;
            h[q * 2 + 1] = *(uint32_t*)&hh1;
            l[q * 2]     = *(uint32_t*)&ll0;
            l[q * 2 + 1] = *(uint32_t*)&ll1;
        }
        asm volatile("st.shared.v4.b32 [%0], {%1, %2, %3, %4};" ::
            "r"(base), "r"(h[0]), "r"(h[1]), "r"(h[2]), "r"(h[3]));
        asm volatile("st.shared.v4.b32 [%0], {%1, %2, %3, %4};" ::
            "r"(base + BUFB), "r"(l[0]), "r"(l[1]), "r"(l[2]), "r"(l[3]));
    };
    auto issueB = [&](int s) {
        const int kc = s * 16;
        const uint32_t d = sb + (uint32_t)((s & 3) * STG) + dstBase;
        const long boff = (long)arow * KP_IN + kc + c8 * 8;
        CPA16(d + 2 * BUFB, pBh + boff);
        CPA16(d + 3 * BUFB, pBl + boff);
    };

    const uint32_t aOff = (uint32_t)(((wm * 32 + (lane & 15)) * TS + (lane >> 4) * 8) * 2);
    const uint32_t bOff = (uint32_t)(((wn * 64 + (lane & 7) + ((lane >= 16) ? 8 : 0)) * TS
                                     + ((lane >> 3) & 1) * 8) * 2);

    const int nst = KP_IN >> 4;   // 30
    float4 fl[2];
#pragma unroll
    for (int s = 0; s < 3; s++) {
        loadA8(fl, s * 16);
        issueB(s); CPC();
        storeA(fl, s);
    }

    for (int c = 0; c < nst; c++) {
        CPW2();
        __syncthreads();
        const bool more = (c + 3 < nst);
        if (more) { issueB(c + 3); loadA8(fl, (c + 3) * 16); }
        CPC();

        const uint32_t base = sb + (uint32_t)((c & 3) * STG);
        uint32_t ah[2][4], al[2][4];
#pragma unroll
        for (int mt = 0; mt < 2; mt++) {
            const uint32_t ao = aOff + (uint32_t)(mt * 16 * TS * 2);
            LDSM4(ah[mt][0], ah[mt][1], ah[mt][2], ah[mt][3], base + ao);
            LDSM4(al[mt][0], al[mt][1], al[mt][2], al[mt][3], base + BUFB + ao);
        }
#pragma unroll
        for (int p = 0; p < 4; p++) {
            const uint32_t bo = bOff + (uint32_t)(p * 16 * TS * 2);
            uint32_t bh[4], bl[4];
            LDSM4(bh[0], bh[1], bh[2], bh[3], base + 2 * BUFB + bo);
            LDSM4(bl[0], bl[1], bl[2], bl[3], base + 3 * BUFB + bo);
#pragma unroll
            for (int mt = 0; mt < 2; mt++) {
                MMA_F16(acc[mt][2 * p],     ah[mt], bh[0], bh[1]);
                MMA_F16(acc[mt][2 * p],     al[mt], bh[0], bh[1]);
                MMA_F16(acc[mt][2 * p],     ah[mt], bl[0], bl[1]);
                MMA_F16(acc[mt][2 * p + 1], ah[mt], bh[2], bh[3]);
                MMA_F16(acc[mt][2 * p + 1], al[mt], bh[2], bh[3]);
                MMA_F16(acc[mt][2 * p + 1], ah[mt], bl[2], bl[3]);
            }
        }
        if (more) storeA(fl, c + 3);
    }

    // epilogue: bias + lrelu, split to half pairs; cols<256 -> sa, else -> ci
#pragma unroll
    for (int mt = 0; mt < 2; mt++) {
        const int row = rowBase + wm * 32 + mt * 16 + lr;
#pragma unroll
        for (int nt = 0; nt < 8; nt++) {
            const int gcol = colBase + wn * 64 + nt * 8 + lc * 2;
            float b0 = bes[(long)a * 512 + gcol];
            float b1 = bes[(long)a * 512 + gcol + 1];
            float v0 = acc[mt][nt][0] + b0;
            float v1 = acc[mt][nt][1] + b1;
            float v2 = acc[mt][nt][2] + b0;
            float v3 = acc[mt][nt][3] + b1;
            v0 = v0 > 0.f ? v0 : 0.01f * v0;
            v1 = v1 > 0.f ? v1 : 0.01f * v1;
            v2 = v2 > 0.f ? v2 : 0.01f * v2;
            v3 = v3 > 0.f ? v3 : 0.01f * v3;
            __half* oh; __half* ol; int os; int oc;
            if (gcol < 256) { oh = sah; ol = sal; os = NH;   oc = gcol; }
            else            { oh = cih; ol = cil; os = KP_C; oc = gcol - 256; }
            __half h0, l0, h1, l1, h2, l2, h3, l3;
            split_h(v0, h0, l0); split_h(v1, h1, l1);
            split_h(v2, h2, l2); split_h(v3, h3, l3);
            long i0 = ((long)a * NB + row) * os + oc;
            long i1 = ((long)a * NB + row + 8) * os + oc;
            *(__half2*)(oh + i0) = __halves2half2(h0, h1);
            *(__half2*)(ol + i0) = __halves2half2(l0, l1);
            *(__half2*)(oh + i1) = __halves2half2(h2, h3);
            *(__half2*)(ol + i1) = __halves2half2(l2, l3);
        }
    }
}

// ---------------- generic half-pair-in, fp32-out GEMM -----------------------
__global__ __launch_bounds__(256, 2)
void gemmH(const __half* __restrict__ Ah, const __half* __restrict__ Al,
           int astride, int Kpad,
           const __half* __restrict__ Bh, const __half* __restrict__ Bl,
           long wstride, const float* __restrict__ bias, long bstride, int act,
           float* __restrict__ Yf, float* __restrict__ Yf2)
{
    extern __shared__ char smem[];
    const uint32_t sb = s2u(smem);

    const int a = blockIdx.z;
    const int tid = threadIdx.x;
    const int lane = tid & 31;
    const int wid = tid >> 5;
    const int wm = wid & 3;
    const int wn = wid >> 2;
    const int lr = lane >> 2;
    const int lc = lane & 3;
    const int rowBase = blockIdx.y * 128;
    const int colBase = blockIdx.x * 128;

    const __half* pAh = Ah + (long)a * NB * astride + (long)rowBase * astride;
    const __half* pAl = Al + (long)a * NB * astride + (long)rowBase * astride;
    const __half* pBh = Bh + (long)a * wstride + (long)colBase * Kpad;
    const __half* pBl = Bl + (long)a * wstride + (long)colBase * Kpad;

    float acc[2][8][4];
#pragma unroll
    for (int mt = 0; mt < 2; mt++)
#pragma unroll
        for (int nt = 0; nt < 8; nt++)
#pragma unroll
            for (int j = 0; j < 4; j++) acc[mt][nt][j] = 0.f;

    const int arow = tid >> 1;
    const int c8   = tid & 1;
    const uint32_t dstBase = (uint32_t)(arow * (TS * 2) + c8 * 16);

    auto issueStage = [&](int s) {
        const int kc = s * 16;
        const uint32_t d = sb + (uint32_t)((s & 3) * STG) + dstBase;
        const long aoff = (long)arow * astride + kc + c8 * 8;
        const long boff = (long)arow * Kpad    + kc + c8 * 8;
        CPA16(d,            pAh + aoff);
        CPA16(d + BUFB,     pAl + aoff);
        CPA16(d + 2 * BUFB, pBh + boff);
        CPA16(d + 3 * BUFB, pBl + boff);
    };

    const uint32_t aOff = (uint32_t)(((wm * 32 + (lane & 15)) * TS + (lane >> 4) * 8) * 2);
    const uint32_t bOff = (uint32_t)(((wn * 64 + (lane & 7) + ((lane >= 16) ? 8 : 0)) * TS
                                     + ((lane >> 3) & 1) * 8) * 2);

    const int nst = Kpad >> 4;
#pragma unroll
    for (int s = 0; s < 3; s++) { issueStage(s); CPC(); }

    for (int c = 0; c < nst; c++) {
        CPW2();
        __syncthreads();
        if (c + 3 < nst) issueStage(c + 3);
        CPC();

        const uint32_t base = sb + (uint32_t)((c & 3) * STG);
        uint32_t ah[2][4], al[2][4];
#pragma unroll
        for (int mt = 0; mt < 2; mt++) {
            const uint32_t ao = aOff + (uint32_t)(mt * 16 * TS * 2);
            LDSM4(ah[mt][0], ah[mt][1], ah[mt][2], ah[mt][3], base + ao);
            LDSM4(al[mt][0], al[mt][1], al[mt][2], al[mt][3], base + BUFB + ao);
        }
#pragma unroll
        for (int p = 0; p < 4; p++) {
            const uint32_t bo = bOff + (uint32_t)(p * 16 * TS * 2);
            uint32_t bh[4], bl[4];
            LDSM4(bh[0], bh[1], bh[2], bh[3], base + 2 * BUFB + bo);
            LDSM4(bl[0], bl[1], bl[2], bl[3], base + 3 * BUFB + bo);
#pragma unroll
            for (int mt = 0; mt < 2; mt++) {
                MMA_F16(acc[mt][2 * p],     ah[mt], bh[0], bh[1]);
                MMA_F16(acc[mt][2 * p],     al[mt], bh[0], bh[1]);
                MMA_F16(acc[mt][2 * p],     ah[mt], bl[0], bl[1]);
                MMA_F16(acc[mt][2 * p + 1], ah[mt], bh[2], bh[3]);
                MMA_F16(acc[mt][2 * p + 1], al[mt], bh[2], bh[3]);
                MMA_F16(acc[mt][2 * p + 1], ah[mt], bl[2], bl[3]);
            }
        }
    }

    // epilogue (fp32 outputs only)
    const bool doAct = (act == 1) || (act == 2 && colBase >= 256);
#pragma unroll
    for (int mt = 0; mt < 2; mt++) {
        const int row = rowBase + wm * 32 + mt * 16 + lr;
#pragma unroll
        for (int nt = 0; nt < 8; nt++) {
            const int gcol = colBase + wn * 64 + nt * 8 + lc * 2;
            float b0 = 0.f, b1 = 0.f;
            if (bias) {
                b0 = bias[(long)a * bstride + gcol];
                b1 = bias[(long)a * bstride + gcol + 1];
            }
            float v0 = acc[mt][nt][0] + b0;
            float v1 = acc[mt][nt][1] + b1;
            float v2 = acc[mt][nt][2] + b0;
            float v3 = acc[mt][nt][3] + b1;
            if (doAct) {
                v0 = v0 > 0.f ? v0 : 0.01f * v0;
                v1 = v1 > 0.f ? v1 : 0.01f * v1;
                v2 = v2 > 0.f ? v2 : 0.01f * v2;
                v3 = v3 > 0.f ? v3 : 0.01f * v3;
            }
            float* Yo = (Yf2 && gcol >= 256) ? Yf2 : Yf;
            const int oc = gcol & 255;
            float2 o0 = {v0, v1};
            float2 o1 = {v2, v3};
            *(float2*)(Yo + ((long)a * NB + row) * NH + oc)     = o0;
            *(float2*)(Yo + ((long)a * NB + row + 8) * NH + oc) = o1;
        }
    }
}

// ---------------- attention over agents ------------------------------------
__global__ __launch_bounds__(256)
void attn_k(const float* __restrict__ keys, const float* __restrict__ sels,
            const float* __restrict__ vals,
            __half* __restrict__ ci_h, __half* __restrict__ ci_l)
{
    const int b = blockIdx.x;
    __shared__ float sk[NA][NH + 4];
    __shared__ float ss[NA][NH + 4];
    __shared__ float sv[NA][NH + 4];
    __shared__ float lg[NE][NA][NA];
    __shared__ float pr[NE][NA][NA];

    const int tid = threadIdx.x;
    for (int i = tid; i < NA * (NH / 4); i += 256) {
        int ag = i >> 6;
        int h4 = (i & 63) * 4;
        long off = ((long)ag * NB + b) * NH + h4;
        *(float4*)&sk[ag][h4] = *(const float4*)(keys + off);
        *(float4*)&ss[ag][h4] = *(const float4*)(sels + off);
        *(float4*)&sv[ag][h4] = *(const float4*)(vals + off);
    }
    __syncthreads();

    {
        int e = tid >> 6;
        int i = (tid >> 3) & 7;
        int j = tid & 7;
        const float* sp = &ss[i][e * ND];
        const float* kp = &sk[j][e * ND];
        float s = 0.f;
#pragma unroll
        for (int d = 0; d < ND; d++) s = fmaf(sp[d], kp[d], s);
        lg[e][i][j] = (i == j) ? -1e9f : s * 0.125f;
    }
    __syncthreads();

    if (tid < NE * NA) {
        int e = tid >> 3;
        int i = tid & 7;
        float mx = -1e30f;
#pragma unroll
        for (int j = 0; j < NA; j++) mx = fmaxf(mx, lg[e][i][j]);
        float p[NA]; float sum = 0.f;
#pragma unroll
        for (int j = 0; j < NA; j++) { p[j] = expf(lg[e][i][j] - mx); sum += p[j]; }
        float inv = 1.f / sum;
#pragma unroll
        for (int j = 0; j < NA; j++) pr[e][i][j] = p[j] * inv;
    }
    __syncthreads();

    for (int o = tid; o < NA * NH; o += 256) {
        int i = o >> 8;
        int h = o & 255;
        int e = h >> 6;
        float s = 0.f;
#pragma unroll
        for (int j = 0; j < NA; j++) s = fmaf(pr[e][i][j], sv[j][h], s);
        __half hv, lv; split_h(s, hv, lv);
        long idx = ((long)i * NB + b) * KP_C + NH + h;
        ci_h[idx] = hv;
        ci_l[idx] = lv;
    }
}

// ---------------- final: argmax(actions) + q -------------------------------
__global__ __launch_bounds__(256)
void q_k(const float* __restrict__ hbuf, const float* __restrict__ actions,
         const float* __restrict__ c_W2, const float* __restrict__ c_b2,
         float* __restrict__ q)
{
    const int gw = (blockIdx.x * blockDim.x + threadIdx.x) >> 5;
    const int lane = threadIdx.x & 31;
    if (gw >= NA * NB) return;
    const int a = gw >> 14;
    const int b = gw & (NB - 1);

    const float* ap = actions + ((long)a * NB + b) * NACT;
    float av = (lane < NACT) ? ap[lane] : -1e30f;
    int ai = lane;
#pragma unroll
    for (int off = 16; off > 0; off >>= 1) {
        float ov = __shfl_down_sync(0xFFFFFFFFu, av, off);
        int   oi = __shfl_down_sync(0xFFFFFFFFu, ai, off);
        if (ov > av || (ov == av && oi < ai)) { av = ov; ai = oi; }
    }
    ai = __shfl_sync(0xFFFFFFFFu, ai, 0);

    const float* hp = hbuf + ((long)a * NB + b) * NH;
    const float* wp = c_W2 + (long)a * NH * NACT + ai;
    float s = 0.f;
#pragma unroll
    for (int it = 0; it < NH / 32; it++) {
        int h = lane + it * 32;
        s = fmaf(hp[h], wp[(long)h * NACT], s);
    }
#pragma unroll
    for (int off = 16; off > 0; off >>= 1)
        s += __shfl_down_sync(0xFFFFFFFFu, s, off);
    if (lane == 0) q[gw] = s + c_b2[a * NACT + ai];
}

// ---------------- launcher --------------------------------------------------
extern "C" void kernel_launch(void* const* d_in, const int* in_sizes, int n_in,
                              void* d_out, int out_size)
{
    const float* states  = (const float*)d_in[0];
    const float* actions = (const float*)d_in[1];
    const float* enc_W   = (const float*)d_in[2];
    const float* enc_b   = (const float*)d_in[3];
    const float* s_W     = (const float*)d_in[4];
    const float* s_b     = (const float*)d_in[5];
    const float* key_W   = (const float*)d_in[6];
    const float* sel_W   = (const float*)d_in[7];
    const float* val_W   = (const float*)d_in[8];
    const float* val_b   = (const float*)d_in[9];
    const float* c_W1    = (const float*)d_in[10];
    const float* c_b1    = (const float*)d_in[11];
    const float* c_W2    = (const float*)d_in[12];
    const float* c_b2    = (const float*)d_in[13];
    float* q = (float*)d_out;

    __half *sah, *sal, *cih, *cil;
    cudaGetSymbolAddress((void**)&sah, g_sa_h);
    cudaGetSymbolAddress((void**)&sal, g_sa_l);
    cudaGetSymbolAddress((void**)&cih, g_ci_h);
    cudaGetSymbolAddress((void**)&cil, g_ci_l);
    float *keys, *vals, *sels, *hbuf, *bkv, *bes;
    cudaGetSymbolAddress((void**)&keys, g_keys);
    cudaGetSymbolAddress((void**)&vals, g_vals);
    cudaGetSymbolAddress((void**)&sels, g_sels);
    cudaGetSymbolAddress((void**)&hbuf, g_h);
    cudaGetSymbolAddress((void**)&bkv,  g_bias_kv);
    cudaGetSymbolAddress((void**)&bes,  g_bias_es);
    __half *wESh, *wESl, *wCh, *wCl, *wKVh, *wKVl, *wQh, *wQl;
    cudaGetSymbolAddress((void**)&wESh, g_wES_h);
    cudaGetSymbolAddress((void**)&wESl, g_wES_l);
    cudaGetSymbolAddress((void**)&wCh, g_wC_h);
    cudaGetSymbolAddress((void**)&wCl, g_wC_l);
    cudaGetSymbolAddress((void**)&wKVh, g_wKV_h);
    cudaGetSymbolAddress((void**)&wKVl, g_wKV_l);
    cudaGetSymbolAddress((void**)&wQh, g_wQ_h);
    cudaGetSymbolAddress((void**)&wQl, g_wQ_l);

    cudaFuncSetAttribute(gemmES, cudaFuncAttributeMaxDynamicSharedMemorySize, SMEM_TOT);
    cudaFuncSetAttribute(gemmH,  cudaFuncAttributeMaxDynamicSharedMemorySize, SMEM_TOT);

    // ---- prep: 1 launch -----------------------------------------------------
    prep_all<<<(unsigned)((SEG_END + 255) / 256), 256>>>(
        enc_W, s_W, c_W1, key_W, val_W, sel_W, val_b, enc_b, s_b,
        wESh, wESl, wCh, wCl, wKVh, wKVl, wQh, wQl, bkv, bes);

    dim3 blk(256);
    dim3 grd2(2, NB / 128, NA);
    dim3 grd4(4, NB / 128, NA);

    // 1) fused sa_enc + s_enc (direct fp32 A)
    gemmES<<<grd4, blk, SMEM_TOT>>>(states, actions, wESh, wESl, bes,
                                    sah, sal, cih, cil);

    // 2) keys & vals fused (N=512)
    gemmH<<<grd4, blk, SMEM_TOT>>>(sah, sal, NH, KP_H, wKVh, wKVl,
        0, bkv, 0, 2, keys, vals);

    // 3) sels (A = s_enc inside ci, row stride 512)
    gemmH<<<grd2, blk, SMEM_TOT>>>(cih, cil, KP_C, KP_H, wQh, wQl,
        0, nullptr, 0, 0, sels, nullptr);

    // 4) attention -> ci cols [256,512)
    attn_k<<<NB, 256>>>(keys, sels, vals, cih, cil);

    // 5) h = lrelu(ci @ c_W1 + c_b1)
    gemmH<<<grd2, blk, SMEM_TOT>>>(cih, cil, KP_C, KP_C, wCh, wCl,
        (long)256 * KP_C, c_b1, NH, 1, hbuf, nullptr);

    // 6) q
    q_k<<<(NA * NB * 32) / 256, 256>>>(hbuf, actions, c_W2, c_b2, q);
}

// round 16
// speedup vs baseline: 1.1403x; 1.1403x over previous
#include <cuda_runtime.h>
#include <cuda_fp16.h>
#include <cstdint>

#define NA 8
#define NB 16384
#define NS 456
#define NACT 16
#define NIDIM 472
#define NH 256
#define NE 4
#define ND 64

#define KP_IN  480
#define KP_H   256
#define KP_C   512

// ---------------- scratch (device globals) ----------------------------------
__device__ __half g_sa_h [(size_t)NA * NB * NH];
__device__ __half g_sa_l [(size_t)NA * NB * NH];
__device__ __half g_ci_h [(size_t)NA * NB * KP_C];   // [s_enc | other]
__device__ __half g_ci_l [(size_t)NA * NB * KP_C];
__device__ float g_keys[(size_t)NA * NB * NH];
__device__ float g_vals[(size_t)NA * NB * NH];
__device__ float g_sels[(size_t)NA * NB * NH];
__device__ float g_h   [(size_t)NA * NB * NH];
// fused enc|s weights: [A][512][480]
__device__ __half g_wES_h[(size_t)NA * 512 * KP_IN];
__device__ __half g_wES_l[(size_t)NA * 512 * KP_IN];
__device__ __half g_wC_h [(size_t)NA * 256 * KP_C];
__device__ __half g_wC_l [(size_t)NA * 256 * KP_C];
__device__ __half g_wKV_h[(size_t)512 * 256];        // [keys | vals]
__device__ __half g_wKV_l[(size_t)512 * 256];
__device__ __half g_wQ_h [(size_t)256 * 256];
__device__ __half g_wQ_l [(size_t)256 * 256];
__device__ float g_bias_kv[512];
__device__ float g_bias_es[(size_t)NA * 512];        // [enc_b | s_b]

// ---------------- helpers ----------------------------------------------------
__device__ __forceinline__ uint32_t s2u(const void* p) {
    uint32_t a;
    asm("{ .reg .u64 t; cvta.to.shared.u64 t, %1; cvt.u32.u64 %0, t; }"
        : "=r"(a) : "l"(p));
    return a;
}
#define CPA16(d, s) \
    asm volatile("cp.async.cg.shared.global [%0], [%1], 16;" :: "r"(d), "l"(s))
#define CPC()  asm volatile("cp.async.commit_group;")
#define CPW0() asm volatile("cp.async.wait_group 0;")
#define LDSM4(R0, R1, R2, R3, A) \
    asm volatile("ldmatrix.sync.aligned.m8n8.x4.shared.b16 {%0,%1,%2,%3}, [%4];" \
        : "=r"(R0), "=r"(R1), "=r"(R2), "=r"(R3) : "r"(A))

__device__ __forceinline__ void split_h(float x, __half& hi, __half& lo) {
    hi = __float2half_rn(x);
    lo = __float2half_rn(x - __half2float(hi));
}

#define MMA_F16(d, a, b0, b1) \
    asm volatile("mma.sync.aligned.m16n8k16.row.col.f32.f16.f16.f32 " \
        "{%0,%1,%2,%3}, {%4,%5,%6,%7}, {%8,%9}, {%0,%1,%2,%3};" \
        : "+f"((d)[0]), "+f"((d)[1]), "+f"((d)[2]), "+f"((d)[3]) \
        : "r"((a)[0]), "r"((a)[1]), "r"((a)[2]), "r"((a)[3]), "r"(b0), "r"(b1))

// ---------------- weight prep (one kernel) -----------------------------------
#define SEG_ES  0L
#define SEG_C   1966080L
#define SEG_K   3014656L
#define SEG_V   3080192L
#define SEG_Q   3145728L
#define SEG_BKV 3211264L
#define SEG_BES 3211776L
#define SEG_END 3215872L

__device__ __forceinline__ void hsplit(const float* W, __half* wh, __half* wl, long j)
{
    int k = (int)(j & 255);
    int n = (int)(j >> 8);
    float v = W[((long)(n >> 6) * 256 + k) * 64 + (n & 63)];
    __half h, l; split_h(v, h, l);
    wh[(long)n * 256 + k] = h;
    wl[(long)n * 256 + k] = l;
}

__global__ void prep_all(const float* __restrict__ enc_W, const float* __restrict__ s_W,
                         const float* __restrict__ c_W1, const float* __restrict__ key_W,
                         const float* __restrict__ val_W, const float* __restrict__ sel_W,
                         const float* __restrict__ val_b, const float* __restrict__ enc_b,
                         const float* __restrict__ s_b,
                         __half* wESh, __half* wESl, __half* wCh, __half* wCl,
                         __half* wKVh, __half* wKVl, __half* wQh, __half* wQl,
                         float* bkv, float* bes)
{
    long i = (long)blockIdx.x * 256 + threadIdx.x;
    if (i >= SEG_END) return;
    if (i < SEG_C) {
        long j = i;
        int kp = (int)(j % KP_IN);
        int n  = (int)((j / KP_IN) & 511);
        int a  = (int)(j / ((long)KP_IN * 512));
        float v = 0.f;
        if (n < 256) { if (kp < NIDIM) v = enc_W[((long)a * NIDIM + kp) * 256 + n]; }
        else         { if (kp < NS)    v = s_W[((long)a * NS + kp) * 256 + (n - 256)]; }
        __half h, l; split_h(v, h, l);
        wESh[j] = h; wESl[j] = l;
    } else if (i < SEG_K) {
        long j = i - SEG_C;
        int kp = (int)(j % KP_C);
        int n  = (int)((j / KP_C) & 255);
        int a  = (int)(j / ((long)KP_C * 256));
        float v = c_W1[((long)a * KP_C + kp) * 256 + n];
        __half h, l; split_h(v, h, l);
        wCh[j] = h; wCl[j] = l;
    }
    else if (i < SEG_V)   hsplit(key_W, wKVh, wKVl, i - SEG_K);
    else if (i < SEG_Q)   hsplit(val_W, wKVh + 65536, wKVl + 65536, i - SEG_V);
    else if (i < SEG_BKV) hsplit(sel_W, wQh, wQl, i - SEG_Q);
    else if (i < SEG_BES) {
        int j = (int)(i - SEG_BKV);
        bkv[j] = (j < 256) ? 0.f : val_b[j - 256];
    } else {
        int j = (int)(i - SEG_BES);     // a*512 + n
        int a = j >> 9;
        int n = j & 511;
        bes[j] = (n < 256) ? enc_b[a * 256 + n] : s_b[a * 256 + (n - 256)];
    }
}

// ---------------- shared GEMM plumbing (2-stage x 32-K, R13 config) ----------
#define TS 40
#define BUFB (128 * TS * 2)
#define OFF_AH 0
#define OFF_AL (2 * BUFB)
#define OFF_BH (4 * BUFB)
#define OFF_BL (6 * BUFB)
#define SMEM_TOT (8 * BUFB)

// ---------------- ES GEMM: direct fp32 A (states|actions), half-pair out ----
__global__ __launch_bounds__(256, 2)
void gemmES(const float* __restrict__ st, const float* __restrict__ ac,
            const __half* __restrict__ Bh, const __half* __restrict__ Bl,
            const float* __restrict__ bes,
            __half* __restrict__ sah, __half* __restrict__ sal,
            __half* __restrict__ cih, __half* __restrict__ cil)
{
    extern __shared__ char smem[];
    const uint32_t sb = s2u(smem);

    const int a = blockIdx.z;
    const int tid = threadIdx.x;
    const int lane = tid & 31;
    const int wid = tid >> 5;
    const int wm = wid & 3;
    const int wn = wid >> 2;
    const int lr = lane >> 2;
    const int lc = lane & 3;
    const int rowBase = blockIdx.y * 128;
    const int colBase = blockIdx.x * 128;

    const int arow = tid >> 1;
    const int kb   = (tid & 1) * 16;
    const float* strow = st + ((long)a * NB + rowBase + arow) * NS;
    const float* acrow = ac + ((long)a * NB + rowBase + arow) * NACT;
    const uint32_t aDstH = sb + OFF_AH + (uint32_t)(arow * (TS * 2) + kb * 2);
    const uint32_t aDstL = sb + OFF_AL + (uint32_t)(arow * (TS * 2) + kb * 2);

    const __half* pBh = Bh + (long)a * (512L * KP_IN) + (long)colBase * KP_IN;
    const __half* pBl = Bl + (long)a * (512L * KP_IN) + (long)colBase * KP_IN;

    float acc[2][8][4];
#pragma unroll
    for (int mt = 0; mt < 2; mt++)
#pragma unroll
        for (int nt = 0; nt < 8; nt++)
#pragma unroll
            for (int j = 0; j < 4; j++) acc[mt][nt][j] = 0.f;

    const int rrow = tid >> 2;
    const int grp  = tid & 3;

    auto loadA = [&](float4* v, int kc) {
#pragma unroll
        for (int q = 0; q < 4; q++) {
            const int k = kc + kb + q * 4;
            if (k < NS)          v[q] = *(const float4*)(strow + k);
            else if (k < NIDIM)  v[q] = *(const float4*)(acrow + (k - NS));
            else                 v[q] = make_float4(0.f, 0.f, 0.f, 0.f);
        }
    };
    auto storeA = [&](const float4* v, int buf) {
#pragma unroll
        for (int q = 0; q < 4; q++) {
            __half h0, l0, h1, l1, h2, l2, h3, l3;
            split_h(v[q].x, h0, l0); split_h(v[q].y, h1, l1);
            split_h(v[q].z, h2, l2); split_h(v[q].w, h3, l3);
            __half2 hh0 = __halves2half2(h0, h1), hh1 = __halves2half2(h2, h3);
            __half2 ll0 = __halves2half2(l0, l1), ll1 = __halves2half2(l2, l3);
            uint32_t dH = aDstH + buf * BUFB + q * 8;
            uint32_t dL = aDstL + buf * BUFB + q * 8;
            asm volatile("st.shared.v2.b32 [%0], {%1, %2};" ::
                "r"(dH), "r"(*(uint32_t*)&hh0), "r"(*(uint32_t*)&hh1));
            asm volatile("st.shared.v2.b32 [%0], {%1, %2};" ::
                "r"(dL), "r"(*(uint32_t*)&ll0), "r"(*(uint32_t*)&ll1));
        }
    };
    auto issueB = [&](int buf, int kc) {
#pragma unroll
        for (int t = 0; t < 2; t++) {
            const int row = rrow + t * 64;
            const uint32_t dst = (uint32_t)(row * (TS * 2) + grp * 16);
            const long boff = (long)row * KP_IN + kc + grp * 8;
            CPA16(sb + OFF_BH + buf * BUFB + dst, pBh + boff);
            CPA16(sb + OFF_BL + buf * BUFB + dst, pBl + boff);
        }
    };

    const uint32_t aOff = (uint32_t)(((wm * 32 + (lane & 15)) * TS + (lane >> 4) * 8) * 2);
    const uint32_t bOff = (uint32_t)(((wn * 64 + (lane & 7) + ((lane >= 16) ? 8 : 0)) * TS
                                     + ((lane >> 3) & 1) * 8) * 2);

    const int nst = KP_IN >> 5;   // 15
    float4 av4[4];
    loadA(av4, 0);
    issueB(0, 0); CPC();
    storeA(av4, 0);

    for (int c = 0; c < nst; c++) {
        const int buf = c & 1;
        CPW0();
        __syncthreads();
        if (c + 1 < nst) { loadA(av4, (c + 1) * 32); issueB(buf ^ 1, (c + 1) * 32); CPC(); }

        const uint32_t sAh = sb + OFF_AH + buf * BUFB;
        const uint32_t sAl = sb + OFF_AL + buf * BUFB;
        const uint32_t sBh = sb + OFF_BH + buf * BUFB;
        const uint32_t sBl = sb + OFF_BL + buf * BUFB;

#pragma unroll
        for (int kk = 0; kk < 2; kk++) {
            const uint32_t kbB = kk * 32;
            uint32_t ah[2][4], al[2][4];
#pragma unroll
            for (int mt = 0; mt < 2; mt++) {
                const uint32_t ao = aOff + (uint32_t)(mt * 16 * TS * 2) + kbB;
                LDSM4(ah[mt][0], ah[mt][1], ah[mt][2], ah[mt][3], sAh + ao);
                LDSM4(al[mt][0], al[mt][1], al[mt][2], al[mt][3], sAl + ao);
            }
#pragma unroll
            for (int p = 0; p < 4; p++) {
                const uint32_t bo = bOff + (uint32_t)(p * 16 * TS * 2) + kbB;
                uint32_t bh[4], bl[4];
                LDSM4(bh[0], bh[1], bh[2], bh[3], sBh + bo);
                LDSM4(bl[0], bl[1], bl[2], bl[3], sBl + bo);
#pragma unroll
                for (int mt = 0; mt < 2; mt++) {
                    MMA_F16(acc[mt][2 * p],     ah[mt], bh[0], bh[1]);
                    MMA_F16(acc[mt][2 * p],     al[mt], bh[0], bh[1]);
                    MMA_F16(acc[mt][2 * p],     ah[mt], bl[0], bl[1]);
                    MMA_F16(acc[mt][2 * p + 1], ah[mt], bh[2], bh[3]);
                    MMA_F16(acc[mt][2 * p + 1], al[mt], bh[2], bh[3]);
                    MMA_F16(acc[mt][2 * p + 1], ah[mt], bl[2], bl[3]);
                }
            }
        }
        if (c + 1 < nst) storeA(av4, buf ^ 1);
    }

    // epilogue: bias + lrelu, split to half pairs; cols<256 -> sa, else -> ci
#pragma unroll
    for (int mt = 0; mt < 2; mt++) {
        const int row = rowBase + wm * 32 + mt * 16 + lr;
#pragma unroll
        for (int nt = 0; nt < 8; nt++) {
            const int gcol = colBase + wn * 64 + nt * 8 + lc * 2;
            float b0 = bes[(long)a * 512 + gcol];
            float b1 = bes[(long)a * 512 + gcol + 1];
            float v0 = acc[mt][nt][0] + b0;
            float v1 = acc[mt][nt][1] + b1;
            float v2 = acc[mt][nt][2] + b0;
            float v3 = acc[mt][nt][3] + b1;
            v0 = v0 > 0.f ? v0 : 0.01f * v0;
            v1 = v1 > 0.f ? v1 : 0.01f * v1;
            v2 = v2 > 0.f ? v2 : 0.01f * v2;
            v3 = v3 > 0.f ? v3 : 0.01f * v3;
            __half* oh; __half* ol; int os; int oc;
            if (gcol < 256) { oh = sah; ol = sal; os = NH;   oc = gcol; }
            else            { oh = cih; ol = cil; os = KP_C; oc = gcol - 256; }
            __half h0, l0, h1, l1, h2, l2, h3, l3;
            split_h(v0, h0, l0); split_h(v1, h1, l1);
            split_h(v2, h2, l2); split_h(v3, h3, l3);
            long i0 = ((long)a * NB + row) * os + oc;
            long i1 = ((long)a * NB + row + 8) * os + oc;
            *(__half2*)(oh + i0) = __halves2half2(h0, h1);
            *(__half2*)(ol + i0) = __halves2half2(l0, l1);
            *(__half2*)(oh + i1) = __halves2half2(h2, h3);
            *(__half2*)(ol + i1) = __halves2half2(l2, l3);
        }
    }
}

// ---------------- merged KV + sels GEMM (K=256, shared weights) --------------
// blockIdx.x in [0,6): x<4 -> KV job over sa_enc (N=512); x>=4 -> sels over ci.
__global__ __launch_bounds__(256, 2)
void gemmKVQ(const __half* __restrict__ sah, const __half* __restrict__ sal,
             const __half* __restrict__ cih, const __half* __restrict__ cil,
             const __half* __restrict__ wKVh, const __half* __restrict__ wKVl,
             const __half* __restrict__ wQh, const __half* __restrict__ wQl,
             const float* __restrict__ bkv,
             float* __restrict__ keys, float* __restrict__ vals,
             float* __restrict__ sels)
{
    extern __shared__ char smem[];
    const uint32_t sb = s2u(smem);

    const int a = blockIdx.z;
    const int tid = threadIdx.x;
    const int lane = tid & 31;
    const int wid = tid >> 5;
    const int wm = wid & 3;
    const int wn = wid >> 2;
    const int lr = lane >> 2;
    const int lc = lane & 3;
    const int rowBase = blockIdx.y * 128;

    const bool kvJob = (blockIdx.x < 4);
    const int colBase = (kvJob ? blockIdx.x : (blockIdx.x - 4)) * 128;
    const int astride = kvJob ? NH : KP_C;
    const __half* pAh = (kvJob ? sah : cih) + (long)a * NB * astride + (long)rowBase * astride;
    const __half* pAl = (kvJob ? sal : cil) + (long)a * NB * astride + (long)rowBase * astride;
    const __half* pBh = (kvJob ? wKVh : wQh) + (long)colBase * KP_H;
    const __half* pBl = (kvJob ? wKVl : wQl) + (long)colBase * KP_H;

    float acc[2][8][4];
#pragma unroll
    for (int mt = 0; mt < 2; mt++)
#pragma unroll
        for (int nt = 0; nt < 8; nt++)
#pragma unroll
            for (int j = 0; j < 4; j++) acc[mt][nt][j] = 0.f;

    const int rrow = tid >> 2;
    const int grp  = tid & 3;

    auto issueStage = [&](int buf, int kc) {
#pragma unroll
        for (int t = 0; t < 2; t++) {
            const int row = rrow + t * 64;
            const uint32_t dst = (uint32_t)(row * (TS * 2) + grp * 16);
            const long aoff = (long)row * astride + kc + grp * 8;
            const long boff = (long)row * KP_H   + kc + grp * 8;
            CPA16(sb + OFF_AH + buf * BUFB + dst, pAh + aoff);
            CPA16(sb + OFF_AL + buf * BUFB + dst, pAl + aoff);
            CPA16(sb + OFF_BH + buf * BUFB + dst, pBh + boff);
            CPA16(sb + OFF_BL + buf * BUFB + dst, pBl + boff);
        }
    };

    const uint32_t aOff = (uint32_t)(((wm * 32 + (lane & 15)) * TS + (lane >> 4) * 8) * 2);
    const uint32_t bOff = (uint32_t)(((wn * 64 + (lane & 7) + ((lane >= 16) ? 8 : 0)) * TS
                                     + ((lane >> 3) & 1) * 8) * 2);

    const int nst = KP_H >> 5;   // 8
    issueStage(0, 0); CPC();

    for (int c = 0; c < nst; c++) {
        const int buf = c & 1;
        CPW0();
        __syncthreads();
        if (c + 1 < nst) { issueStage(buf ^ 1, (c + 1) * 32); CPC(); }

        const uint32_t sAh = sb + OFF_AH + buf * BUFB;
        const uint32_t sAl = sb + OFF_AL + buf * BUFB;
        const uint32_t sBh = sb + OFF_BH + buf * BUFB;
        const uint32_t sBl = sb + OFF_BL + buf * BUFB;

#pragma unroll
        for (int kk = 0; kk < 2; kk++) {
            const uint32_t kbB = kk * 32;
            uint32_t ah[2][4], al[2][4];
#pragma unroll
            for (int mt = 0; mt < 2; mt++) {
                const uint32_t ao = aOff + (uint32_t)(mt * 16 * TS * 2) + kbB;
                LDSM4(ah[mt][0], ah[mt][1], ah[mt][2], ah[mt][3], sAh + ao);
                LDSM4(al[mt][0], al[mt][1], al[mt][2], al[mt][3], sAl + ao);
            }
#pragma unroll
            for (int p = 0; p < 4; p++) {
                const uint32_t bo = bOff + (uint32_t)(p * 16 * TS * 2) + kbB;
                uint32_t bh[4], bl[4];
                LDSM4(bh[0], bh[1], bh[2], bh[3], sBh + bo);
                LDSM4(bl[0], bl[1], bl[2], bl[3], sBl + bo);
#pragma unroll
                for (int mt = 0; mt < 2; mt++) {
                    MMA_F16(acc[mt][2 * p],     ah[mt], bh[0], bh[1]);
                    MMA_F16(acc[mt][2 * p],     al[mt], bh[0], bh[1]);
                    MMA_F16(acc[mt][2 * p],     ah[mt], bl[0], bl[1]);
                    MMA_F16(acc[mt][2 * p + 1], ah[mt], bh[2], bh[3]);
                    MMA_F16(acc[mt][2 * p + 1], al[mt], bh[2], bh[3]);
                    MMA_F16(acc[mt][2 * p + 1], ah[mt], bl[2], bl[3]);
                }
            }
        }
    }

    // epilogue
#pragma unroll
    for (int mt = 0; mt < 2; mt++) {
        const int row = rowBase + wm * 32 + mt * 16 + lr;
#pragma unroll
        for (int nt = 0; nt < 8; nt++) {
            const int gcol = colBase + wn * 64 + nt * 8 + lc * 2;
            float b0 = 0.f, b1 = 0.f;
            if (kvJob) { b0 = bkv[gcol]; b1 = bkv[gcol + 1]; }
            float v0 = acc[mt][nt][0] + b0;
            float v1 = acc[mt][nt][1] + b1;
            float v2 = acc[mt][nt][2] + b0;
            float v3 = acc[mt][nt][3] + b1;
            if (kvJob && gcol >= 256) {
                v0 = v0 > 0.f ? v0 : 0.01f * v0;
                v1 = v1 > 0.f ? v1 : 0.01f * v1;
                v2 = v2 > 0.f ? v2 : 0.01f * v2;
                v3 = v3 > 0.f ? v3 : 0.01f * v3;
            }
            float* Yo = kvJob ? ((gcol >= 256) ? vals : keys) : sels;
            const int oc = gcol & 255;
            float2 o0 = {v0, v1};
            float2 o1 = {v2, v3};
            *(float2*)(Yo + ((long)a * NB + row) * NH + oc)     = o0;
            *(float2*)(Yo + ((long)a * NB + row + 8) * NH + oc) = o1;
        }
    }
}

// ---------------- critic GEMM (K=512, per-agent weights, fp32 out) -----------
__global__ __launch_bounds__(256, 2)
void gemmC(const __half* __restrict__ Ah, const __half* __restrict__ Al,
           const __half* __restrict__ Bh, const __half* __restrict__ Bl,
           const float* __restrict__ bias, float* __restrict__ Yf)
{
    extern __shared__ char smem[];
    const uint32_t sb = s2u(smem);

    const int a = blockIdx.z;
    const int tid = threadIdx.x;
    const int lane = tid & 31;
    const int wid = tid >> 5;
    const int wm = wid & 3;
    const int wn = wid >> 2;
    const int lr = lane >> 2;
    const int lc = lane & 3;
    const int rowBase = blockIdx.y * 128;
    const int colBase = blockIdx.x * 128;

    const __half* pAh = Ah + (long)a * NB * KP_C + (long)rowBase * KP_C;
    const __half* pAl = Al + (long)a * NB * KP_C + (long)rowBase * KP_C;
    const __half* pBh = Bh + (long)a * (256L * KP_C) + (long)colBase * KP_C;
    const __half* pBl = Bl + (long)a * (256L * KP_C) + (long)colBase * KP_C;

    float acc[2][8][4];
#pragma unroll
    for (int mt = 0; mt < 2; mt++)
#pragma unroll
        for (int nt = 0; nt < 8; nt++)
#pragma unroll
            for (int j = 0; j < 4; j++) acc[mt][nt][j] = 0.f;

    const int rrow = tid >> 2;
    const int grp  = tid & 3;

    auto issueStage = [&](int buf, int kc) {
#pragma unroll
        for (int t = 0; t < 2; t++) {
            const int row = rrow + t * 64;
            const uint32_t dst = (uint32_t)(row * (TS * 2) + grp * 16);
            const long off = (long)row * KP_C + kc + grp * 8;
            CPA16(sb + OFF_AH + buf * BUFB + dst, pAh + off);
            CPA16(sb + OFF_AL + buf * BUFB + dst, pAl + off);
            CPA16(sb + OFF_BH + buf * BUFB + dst, pBh + off);
            CPA16(sb + OFF_BL + buf * BUFB + dst, pBl + off);
        }
    };

    const uint32_t aOff = (uint32_t)(((wm * 32 + (lane & 15)) * TS + (lane >> 4) * 8) * 2);
    const uint32_t bOff = (uint32_t)(((wn * 64 + (lane & 7) + ((lane >= 16) ? 8 : 0)) * TS
                                     + ((lane >> 3) & 1) * 8) * 2);

    const int nst = KP_C >> 5;   // 16
    issueStage(0, 0); CPC();

    for (int c = 0; c < nst; c++) {
        const int buf = c & 1;
        CPW0();
        __syncthreads();
        if (c + 1 < nst) { issueStage(buf ^ 1, (c + 1) * 32); CPC(); }

        const uint32_t sAh = sb + OFF_AH + buf * BUFB;
        const uint32_t sAl = sb + OFF_AL + buf * BUFB;
        const uint32_t sBh = sb + OFF_BH + buf * BUFB;
        const uint32_t sBl = sb + OFF_BL + buf * BUFB;

#pragma unroll
        for (int kk = 0; kk < 2; kk++) {
            const uint32_t kbB = kk * 32;
            uint32_t ah[2][4], al[2][4];
#pragma unroll
            for (int mt = 0; mt < 2; mt++) {
                const uint32_t ao = aOff + (uint32_t)(mt * 16 * TS * 2) + kbB;
                LDSM4(ah[mt][0], ah[mt][1], ah[mt][2], ah[mt][3], sAh + ao);
                LDSM4(al[mt][0], al[mt][1], al[mt][2], al[mt][3], sAl + ao);
            }
#pragma unroll
            for (int p = 0; p < 4; p++) {
                const uint32_t bo = bOff + (uint32_t)(p * 16 * TS * 2) + kbB;
                uint32_t bh[4], bl[4];
                LDSM4(bh[0], bh[1], bh[2], bh[3], sBh + bo);
                LDSM4(bl[0], bl[1], bl[2], bl[3], sBl + bo);
#pragma unroll
                for (int mt = 0; mt < 2; mt++) {
                    MMA_F16(acc[mt][2 * p],     ah[mt], bh[0], bh[1]);
                    MMA_F16(acc[mt][2 * p],     al[mt], bh[0], bh[1]);
                    MMA_F16(acc[mt][2 * p],     ah[mt], bl[0], bl[1]);
                    MMA_F16(acc[mt][2 * p + 1], ah[mt], bh[2], bh[3]);
                    MMA_F16(acc[mt][2 * p + 1], al[mt], bh[2], bh[3]);
                    MMA_F16(acc[mt][2 * p + 1], ah[mt], bl[2], bl[3]);
                }
            }
        }
    }

#pragma unroll
    for (int mt = 0; mt < 2; mt++) {
        const int row = rowBase + wm * 32 + mt * 16 + lr;
#pragma unroll
        for (int nt = 0; nt < 8; nt++) {
            const int gcol = colBase + wn * 64 + nt * 8 + lc * 2;
            float b0 = bias[(long)a * NH + gcol];
            float b1 = bias[(long)a * NH + gcol + 1];
            float v0 = acc[mt][nt][0] + b0;
            float v1 = acc[mt][nt][1] + b1;
            float v2 = acc[mt][nt][2] + b0;
            float v3 = acc[mt][nt][3] + b1;
            v0 = v0 > 0.f ? v0 : 0.01f * v0;
            v1 = v1 > 0.f ? v1 : 0.01f * v1;
            v2 = v2 > 0.f ? v2 : 0.01f * v2;
            v3 = v3 > 0.f ? v3 : 0.01f * v3;
            float2 o0 = {v0, v1};
            float2 o1 = {v2, v3};
            *(float2*)(Yf + ((long)a * NB + row) * NH + gcol)     = o0;
            *(float2*)(Yf + ((long)a * NB + row + 8) * NH + gcol) = o1;
        }
    }
}

// ---------------- attention over agents ------------------------------------
__global__ __launch_bounds__(256)
void attn_k(const float* __restrict__ keys, const float* __restrict__ sels,
            const float* __restrict__ vals,
            __half* __restrict__ ci_h, __half* __restrict__ ci_l)
{
    const int b = blockIdx.x;
    __shared__ float sk[NA][NH + 4];
    __shared__ float ss[NA][NH + 4];
    __shared__ float sv[NA][NH + 4];
    __shared__ float lg[NE][NA][NA];
    __shared__ float pr[NE][NA][NA];

    const int tid = threadIdx.x;
    for (int i = tid; i < NA * (NH / 4); i += 256) {
        int ag = i >> 6;
        int h4 = (i & 63) * 4;
        long off = ((long)ag * NB + b) * NH + h4;
        *(float4*)&sk[ag][h4] = *(const float4*)(keys + off);
        *(float4*)&ss[ag][h4] = *(const float4*)(sels + off);
        *(float4*)&sv[ag][h4] = *(const float4*)(vals + off);
    }
    __syncthreads();

    {
        int e = tid >> 6;
        int i = (tid >> 3) & 7;
        int j = tid & 7;
        const float* sp = &ss[i][e * ND];
        const float* kp = &sk[j][e * ND];
        float s = 0.f;
#pragma unroll
        for (int d = 0; d < ND; d++) s = fmaf(sp[d], kp[d], s);
        lg[e][i][j] = (i == j) ? -1e9f : s * 0.125f;
    }
    __syncthreads();

    if (tid < NE * NA) {
        int e = tid >> 3;
        int i = tid & 7;
        float mx = -1e30f;
#pragma unroll
        for (int j = 0; j < NA; j++) mx = fmaxf(mx, lg[e][i][j]);
        float p[NA]; float sum = 0.f;
#pragma unroll
        for (int j = 0; j < NA; j++) { p[j] = expf(lg[e][i][j] - mx); sum += p[j]; }
        float inv = 1.f / sum;
#pragma unroll
        for (int j = 0; j < NA; j++) pr[e][i][j] = p[j] * inv;
    }
    __syncthreads();

    for (int o = tid; o < NA * NH; o += 256) {
        int i = o >> 8;
        int h = o & 255;
        int e = h >> 6;
        float s = 0.f;
#pragma unroll
        for (int j = 0; j < NA; j++) s = fmaf(pr[e][i][j], sv[j][h], s);
        __half hv, lv; split_h(s, hv, lv);
        long idx = ((long)i * NB + b) * KP_C + NH + h;
        ci_h[idx] = hv;
        ci_l[idx] = lv;
    }
}

// ---------------- final: argmax(actions) + q -------------------------------
__global__ __launch_bounds__(256)
void q_k(const float* __restrict__ hbuf, const float* __restrict__ actions,
         const float* __restrict__ c_W2, const float* __restrict__ c_b2,
         float* __restrict__ q)
{
    const int gw = (blockIdx.x * blockDim.x + threadIdx.x) >> 5;
    const int lane = threadIdx.x & 31;
    if (gw >= NA * NB) return;
    const int a = gw >> 14;
    const int b = gw & (NB - 1);

    const float* ap = actions + ((long)a * NB + b) * NACT;
    float av = (lane < NACT) ? ap[lane] : -1e30f;
    int ai = lane;
#pragma unroll
    for (int off = 16; off > 0; off >>= 1) {
        float ov = __shfl_down_sync(0xFFFFFFFFu, av, off);
        int   oi = __shfl_down_sync(0xFFFFFFFFu, ai, off);
        if (ov > av || (ov == av && oi < ai)) { av = ov; ai = oi; }
    }
    ai = __shfl_sync(0xFFFFFFFFu, ai, 0);

    const float* hp = hbuf + ((long)a * NB + b) * NH;
    const float* wp = c_W2 + (long)a * NH * NACT + ai;
    float s = 0.f;
#pragma unroll
    for (int it = 0; it < NH / 32; it++) {
        int h = lane + it * 32;
        s = fmaf(hp[h], wp[(long)h * NACT], s);
    }
#pragma unroll
    for (int off = 16; off > 0; off >>= 1)
        s += __shfl_down_sync(0xFFFFFFFFu, s, off);
    if (lane == 0) q[gw] = s + c_b2[a * NACT + ai];
}

// ---------------- launcher --------------------------------------------------
extern "C" void kernel_launch(void* const* d_in, const int* in_sizes, int n_in,
                              void* d_out, int out_size)
{
    const float* states  = (const float*)d_in[0];
    const float* actions = (const float*)d_in[1];
    const float* enc_W   = (const float*)d_in[2];
    const float* enc_b   = (const float*)d_in[3];
    const float* s_W     = (const float*)d_in[4];
    const float* s_b     = (const float*)d_in[5];
    const float* key_W   = (const float*)d_in[6];
    const float* sel_W   = (const float*)d_in[7];
    const float* val_W   = (const float*)d_in[8];
    const float* val_b   = (const float*)d_in[9];
    const float* c_W1    = (const float*)d_in[10];
    const float* c_b1    = (const float*)d_in[11];
    const float* c_W2    = (const float*)d_in[12];
    const float* c_b2    = (const float*)d_in[13];
    float* q = (float*)d_out;

    __half *sah, *sal, *cih, *cil;
    cudaGetSymbolAddress((void**)&sah, g_sa_h);
    cudaGetSymbolAddress((void**)&sal, g_sa_l);
    cudaGetSymbolAddress((void**)&cih, g_ci_h);
    cudaGetSymbolAddress((void**)&cil, g_ci_l);
    float *keys, *vals, *sels, *hbuf, *bkv, *bes;
    cudaGetSymbolAddress((void**)&keys, g_keys);
    cudaGetSymbolAddress((void**)&vals, g_vals);
    cudaGetSymbolAddress((void**)&sels, g_sels);
    cudaGetSymbolAddress((void**)&hbuf, g_h);
    cudaGetSymbolAddress((void**)&bkv,  g_bias_kv);
    cudaGetSymbolAddress((void**)&bes,  g_bias_es);
    __half *wESh, *wESl, *wCh, *wCl, *wKVh, *wKVl, *wQh, *wQl;
    cudaGetSymbolAddress((void**)&wESh, g_wES_h);
    cudaGetSymbolAddress((void**)&wESl, g_wES_l);
    cudaGetSymbolAddress((void**)&wCh, g_wC_h);
    cudaGetSymbolAddress((void**)&wCl, g_wC_l);
    cudaGetSymbolAddress((void**)&wKVh, g_wKV_h);
    cudaGetSymbolAddress((void**)&wKVl, g_wKV_l);
    cudaGetSymbolAddress((void**)&wQh, g_wQ_h);
    cudaGetSymbolAddress((void**)&wQl, g_wQ_l);

    cudaFuncSetAttribute(gemmES,  cudaFuncAttributeMaxDynamicSharedMemorySize, SMEM_TOT);
    cudaFuncSetAttribute(gemmKVQ, cudaFuncAttributeMaxDynamicSharedMemorySize, SMEM_TOT);
    cudaFuncSetAttribute(gemmC,   cudaFuncAttributeMaxDynamicSharedMemorySize, SMEM_TOT);

    // ---- prep: 1 launch -----------------------------------------------------
    prep_all<<<(unsigned)((SEG_END + 255) / 256), 256>>>(
        enc_W, s_W, c_W1, key_W, val_W, sel_W, val_b, enc_b, s_b,
        wESh, wESl, wCh, wCl, wKVh, wKVl, wQh, wQl, bkv, bes);

    dim3 blk(256);

    // 1) fused sa_enc + s_enc (direct fp32 A)
    gemmES<<<dim3(4, NB / 128, NA), blk, SMEM_TOT>>>(
        states, actions, wESh, wESl, bes, sah, sal, cih, cil);

    // 2) merged keys|vals (N=512) + sels (N=256) in one launch
    gemmKVQ<<<dim3(6, NB / 128, NA), blk, SMEM_TOT>>>(
        sah, sal, cih, cil, wKVh, wKVl, wQh, wQl, bkv, keys, vals, sels);

    // 3) attention -> ci cols [256,512)
    attn_k<<<NB, 256>>>(keys, sels, vals, cih, cil);

    // 4) h = lrelu(ci @ c_W1 + c_b1)
    gemmC<<<dim3(2, NB / 128, NA), blk, SMEM_TOT>>>(cih, cil, wCh, wCl, c_b1, hbuf);

    // 5) q
    q_k<<<(NA * NB * 32) / 256, 256>>>(hbuf, actions, c_W2, c_b2, q);
}

// round 17
// speedup vs baseline: 1.1467x; 1.0057x over previous
#include <cuda_runtime.h>
#include <cuda_fp16.h>
#include <cstdint>

#define NA 8
#define NB 16384
#define NS 456
#define NACT 16
#define NIDIM 472
#define NH 256
#define NE 4
#define ND 64

#define KP_IN  480
#define KP_H   256
#define KP_C   512

// ---------------- scratch (device globals) ----------------------------------
__device__ __half g_sa_h [(size_t)NA * NB * NH];
__device__ __half g_sa_l [(size_t)NA * NB * NH];
__device__ __half g_ci_h [(size_t)NA * NB * KP_C];   // [s_enc | other]
__device__ __half g_ci_l [(size_t)NA * NB * KP_C];
__device__ float g_keys[(size_t)NA * NB * NH];
__device__ float g_vals[(size_t)NA * NB * NH];
__device__ float g_sels[(size_t)NA * NB * NH];
__device__ float g_h   [(size_t)NA * NB * NH];
// fused enc|s weights: [A][512][480]
__device__ __half g_wES_h[(size_t)NA * 512 * KP_IN];
__device__ __half g_wES_l[(size_t)NA * 512 * KP_IN];
__device__ __half g_wC_h [(size_t)NA * 256 * KP_C];
__device__ __half g_wC_l [(size_t)NA * 256 * KP_C];
__device__ __half g_wKV_h[(size_t)512 * 256];        // [keys | vals]
__device__ __half g_wKV_l[(size_t)512 * 256];
__device__ __half g_wQ_h [(size_t)256 * 256];
__device__ __half g_wQ_l [(size_t)256 * 256];
__device__ float g_bias_kv[512];
__device__ float g_bias_es[(size_t)NA * 512];        // [enc_b | s_b]

// ---------------- helpers ----------------------------------------------------
__device__ __forceinline__ uint32_t s2u(const void* p) {
    uint32_t a;
    asm("{ .reg .u64 t; cvta.to.shared.u64 t, %1; cvt.u32.u64 %0, t; }"
        : "=r"(a) : "l"(p));
    return a;
}
#define CPA16(d, s) \
    asm volatile("cp.async.cg.shared.global [%0], [%1], 16;" :: "r"(d), "l"(s))
#define CPC()  asm volatile("cp.async.commit_group;")
#define CPW0() asm volatile("cp.async.wait_group 0;")
#define LDSM4(R0, R1, R2, R3, A) \
    asm volatile("ldmatrix.sync.aligned.m8n8.x4.shared.b16 {%0,%1,%2,%3}, [%4];" \
        : "=r"(R0), "=r"(R1), "=r"(R2), "=r"(R3) : "r"(A))

__device__ __forceinline__ void split_h(float x, __half& hi, __half& lo) {
    hi = __float2half_rn(x);
    lo = __float2half_rn(x - __half2float(hi));
}

#define MMA_F16(d, a, b0, b1) \
    asm volatile("mma.sync.aligned.m16n8k16.row.col.f32.f16.f16.f32 " \
        "{%0,%1,%2,%3}, {%4,%5,%6,%7}, {%8,%9}, {%0,%1,%2,%3};" \
        : "+f"((d)[0]), "+f"((d)[1]), "+f"((d)[2]), "+f"((d)[3]) \
        : "r"((a)[0]), "r"((a)[1]), "r"((a)[2]), "r"((a)[3]), "r"(b0), "r"(b1))

// ---------------- weight prep (one kernel) -----------------------------------
#define SEG_ES  0L
#define SEG_C   1966080L
#define SEG_K   3014656L
#define SEG_V   3080192L
#define SEG_Q   3145728L
#define SEG_BKV 3211264L
#define SEG_BES 3211776L
#define SEG_END 3215872L

__device__ __forceinline__ void hsplit(const float* W, __half* wh, __half* wl, long j)
{
    int k = (int)(j & 255);
    int n = (int)(j >> 8);
    float v = W[((long)(n >> 6) * 256 + k) * 64 + (n & 63)];
    __half h, l; split_h(v, h, l);
    wh[(long)n * 256 + k] = h;
    wl[(long)n * 256 + k] = l;
}

__global__ void prep_all(const float* __restrict__ enc_W, const float* __restrict__ s_W,
                         const float* __restrict__ c_W1, const float* __restrict__ key_W,
                         const float* __restrict__ val_W, const float* __restrict__ sel_W,
                         const float* __restrict__ val_b, const float* __restrict__ enc_b,
                         const float* __restrict__ s_b,
                         __half* wESh, __half* wESl, __half* wCh, __half* wCl,
                         __half* wKVh, __half* wKVl, __half* wQh, __half* wQl,
                         float* bkv, float* bes)
{
    long i = (long)blockIdx.x * 256 + threadIdx.x;
    if (i >= SEG_END) return;
    if (i < SEG_C) {
        long j = i;
        int kp = (int)(j % KP_IN);
        int n  = (int)((j / KP_IN) & 511);
        int a  = (int)(j / ((long)KP_IN * 512));
        float v = 0.f;
        if (n < 256) { if (kp < NIDIM) v = enc_W[((long)a * NIDIM + kp) * 256 + n]; }
        else         { if (kp < NS)    v = s_W[((long)a * NS + kp) * 256 + (n - 256)]; }
        __half h, l; split_h(v, h, l);
        wESh[j] = h; wESl[j] = l;
    } else if (i < SEG_K) {
        long j = i - SEG_C;
        int kp = (int)(j % KP_C);
        int n  = (int)((j / KP_C) & 255);
        int a  = (int)(j / ((long)KP_C * 256));
        float v = c_W1[((long)a * KP_C + kp) * 256 + n];
        __half h, l; split_h(v, h, l);
        wCh[j] = h; wCl[j] = l;
    }
    else if (i < SEG_V)   hsplit(key_W, wKVh, wKVl, i - SEG_K);
    else if (i < SEG_Q)   hsplit(val_W, wKVh + 65536, wKVl + 65536, i - SEG_V);
    else if (i < SEG_BKV) hsplit(sel_W, wQh, wQl, i - SEG_Q);
    else if (i < SEG_BES) {
        int j = (int)(i - SEG_BKV);
        bkv[j] = (j < 256) ? 0.f : val_b[j - 256];
    } else {
        int j = (int)(i - SEG_BES);     // a*512 + n
        int a = j >> 9;
        int n = j & 511;
        bes[j] = (n < 256) ? enc_b[a * 256 + n] : s_b[a * 256 + (n - 256)];
    }
}

// ---------------- shared GEMM plumbing (2-stage x 32-K) ----------------------
#define TS 40
#define BUFB (128 * TS * 2)
#define OFF_AH 0
#define OFF_AL (2 * BUFB)
#define OFF_BH (4 * BUFB)
#define OFF_BL (6 * BUFB)
#define SMEM_TOT (8 * BUFB)

// ---------------- ES GEMM: direct fp32 A (states|actions), half-pair out ----
__global__ __launch_bounds__(256, 2)
void gemmES(const float* __restrict__ st, const float* __restrict__ ac,
            const __half* __restrict__ Bh, const __half* __restrict__ Bl,
            const float* __restrict__ bes,
            __half* __restrict__ sah, __half* __restrict__ sal,
            __half* __restrict__ cih, __half* __restrict__ cil)
{
    extern __shared__ char smem[];
    const uint32_t sb = s2u(smem);

    const int a = blockIdx.z;
    const int tid = threadIdx.x;
    const int lane = tid & 31;
    const int wid = tid >> 5;
    const int wm = wid & 3;
    const int wn = wid >> 2;
    const int lr = lane >> 2;
    const int lc = lane & 3;
    const int rowBase = blockIdx.y * 128;
    const int colBase = blockIdx.x * 128;

    const int arow = tid >> 1;
    const int kb   = (tid & 1) * 16;
    const float* strow = st + ((long)a * NB + rowBase + arow) * NS;
    const float* acrow = ac + ((long)a * NB + rowBase + arow) * NACT;
    const uint32_t aDstH = sb + OFF_AH + (uint32_t)(arow * (TS * 2) + kb * 2);
    const uint32_t aDstL = sb + OFF_AL + (uint32_t)(arow * (TS * 2) + kb * 2);

    const __half* pBh = Bh + (long)a * (512L * KP_IN) + (long)colBase * KP_IN;
    const __half* pBl = Bl + (long)a * (512L * KP_IN) + (long)colBase * KP_IN;

    float acc[2][8][4];
#pragma unroll
    for (int mt = 0; mt < 2; mt++)
#pragma unroll
        for (int nt = 0; nt < 8; nt++)
#pragma unroll
            for (int j = 0; j < 4; j++) acc[mt][nt][j] = 0.f;

    const int rrow = tid >> 2;
    const int grp  = tid & 3;

    auto loadA = [&](float4* v, int kc) {
#pragma unroll
        for (int q = 0; q < 4; q++) {
            const int k = kc + kb + q * 4;
            if (k < NS)          v[q] = *(const float4*)(strow + k);
            else if (k < NIDIM)  v[q] = *(const float4*)(acrow + (k - NS));
            else                 v[q] = make_float4(0.f, 0.f, 0.f, 0.f);
        }
    };
    auto storeA = [&](const float4* v, int buf) {
#pragma unroll
        for (int q = 0; q < 4; q++) {
            __half h0, l0, h1, l1, h2, l2, h3, l3;
            split_h(v[q].x, h0, l0); split_h(v[q].y, h1, l1);
            split_h(v[q].z, h2, l2); split_h(v[q].w, h3, l3);
            __half2 hh0 = __halves2half2(h0, h1), hh1 = __halves2half2(h2, h3);
            __half2 ll0 = __halves2half2(l0, l1), ll1 = __halves2half2(l2, l3);
            uint32_t dH = aDstH + buf * BUFB + q * 8;
            uint32_t dL = aDstL + buf * BUFB + q * 8;
            asm volatile("st.shared.v2.b32 [%0], {%1, %2};" ::
                "r"(dH), "r"(*(uint32_t*)&hh0), "r"(*(uint32_t*)&hh1));
            asm volatile("st.shared.v2.b32 [%0], {%1, %2};" ::
                "r"(dL), "r"(*(uint32_t*)&ll0), "r"(*(uint32_t*)&ll1));
        }
    };
    auto issueB = [&](int buf, int kc) {
#pragma unroll
        for (int t = 0; t < 2; t++) {
            const int row = rrow + t * 64;
            const uint32_t dst = (uint32_t)(row * (TS * 2) + grp * 16);
            const long boff = (long)row * KP_IN + kc + grp * 8;
            CPA16(sb + OFF_BH + buf * BUFB + dst, pBh + boff);
            CPA16(sb + OFF_BL + buf * BUFB + dst, pBl + boff);
        }
    };

    const uint32_t aOff = (uint32_t)(((wm * 32 + (lane & 15)) * TS + (lane >> 4) * 8) * 2);
    const uint32_t bOff = (uint32_t)(((wn * 64 + (lane & 7) + ((lane >= 16) ? 8 : 0)) * TS
                                     + ((lane >> 3) & 1) * 8) * 2);

    const int nst = KP_IN >> 5;   // 15
    float4 av4[4];
    loadA(av4, 0);
    issueB(0, 0); CPC();
    storeA(av4, 0);

    for (int c = 0; c < nst; c++) {
        const int buf = c & 1;
        CPW0();
        __syncthreads();
        if (c + 1 < nst) { loadA(av4, (c + 1) * 32); issueB(buf ^ 1, (c + 1) * 32); CPC(); }

        const uint32_t sAh = sb + OFF_AH + buf * BUFB;
        const uint32_t sAl = sb + OFF_AL + buf * BUFB;
        const uint32_t sBh = sb + OFF_BH + buf * BUFB;
        const uint32_t sBl = sb + OFF_BL + buf * BUFB;

#pragma unroll
        for (int kk = 0; kk < 2; kk++) {
            const uint32_t kbB = kk * 32;
            uint32_t ah[2][4], al[2][4];
#pragma unroll
            for (int mt = 0; mt < 2; mt++) {
                const uint32_t ao = aOff + (uint32_t)(mt * 16 * TS * 2) + kbB;
                LDSM4(ah[mt][0], ah[mt][1], ah[mt][2], ah[mt][3], sAh + ao);
                LDSM4(al[mt][0], al[mt][1], al[mt][2], al[mt][3], sAl + ao);
            }
#pragma unroll
            for (int p = 0; p < 4; p++) {
                const uint32_t bo = bOff + (uint32_t)(p * 16 * TS * 2) + kbB;
                uint32_t bh[4], bl[4];
                LDSM4(bh[0], bh[1], bh[2], bh[3], sBh + bo);
                LDSM4(bl[0], bl[1], bl[2], bl[3], sBl + bo);
#pragma unroll
                for (int mt = 0; mt < 2; mt++) {
                    MMA_F16(acc[mt][2 * p],     ah[mt], bh[0], bh[1]);
                    MMA_F16(acc[mt][2 * p],     al[mt], bh[0], bh[1]);
                    MMA_F16(acc[mt][2 * p],     ah[mt], bl[0], bl[1]);
                    MMA_F16(acc[mt][2 * p + 1], ah[mt], bh[2], bh[3]);
                    MMA_F16(acc[mt][2 * p + 1], al[mt], bh[2], bh[3]);
                    MMA_F16(acc[mt][2 * p + 1], ah[mt], bl[2], bl[3]);
                }
            }
        }
        if (c + 1 < nst) storeA(av4, buf ^ 1);
    }

    // epilogue: bias + lrelu, split to half pairs; cols<256 -> sa, else -> ci
#pragma unroll
    for (int mt = 0; mt < 2; mt++) {
        const int row = rowBase + wm * 32 + mt * 16 + lr;
#pragma unroll
        for (int nt = 0; nt < 8; nt++) {
            const int gcol = colBase + wn * 64 + nt * 8 + lc * 2;
            float b0 = bes[(long)a * 512 + gcol];
            float b1 = bes[(long)a * 512 + gcol + 1];
            float v0 = acc[mt][nt][0] + b0;
            float v1 = acc[mt][nt][1] + b1;
            float v2 = acc[mt][nt][2] + b0;
            float v3 = acc[mt][nt][3] + b1;
            v0 = v0 > 0.f ? v0 : 0.01f * v0;
            v1 = v1 > 0.f ? v1 : 0.01f * v1;
            v2 = v2 > 0.f ? v2 : 0.01f * v2;
            v3 = v3 > 0.f ? v3 : 0.01f * v3;
            __half* oh; __half* ol; int os; int oc;
            if (gcol < 256) { oh = sah; ol = sal; os = NH;   oc = gcol; }
            else            { oh = cih; ol = cil; os = KP_C; oc = gcol - 256; }
            __half h0, l0, h1, l1, h2, l2, h3, l3;
            split_h(v0, h0, l0); split_h(v1, h1, l1);
            split_h(v2, h2, l2); split_h(v3, h3, l3);
            long i0 = ((long)a * NB + row) * os + oc;
            long i1 = ((long)a * NB + row + 8) * os + oc;
            *(__half2*)(oh + i0) = __halves2half2(h0, h1);
            *(__half2*)(ol + i0) = __halves2half2(l0, l1);
            *(__half2*)(oh + i1) = __halves2half2(h2, h3);
            *(__half2*)(ol + i1) = __halves2half2(l2, l3);
        }
    }
}

// ---------------- merged KV + sels GEMM (K=256, shared weights) --------------
__global__ __launch_bounds__(256, 2)
void gemmKVQ(const __half* __restrict__ sah, const __half* __restrict__ sal,
             const __half* __restrict__ cih, const __half* __restrict__ cil,
             const __half* __restrict__ wKVh, const __half* __restrict__ wKVl,
             const __half* __restrict__ wQh, const __half* __restrict__ wQl,
             const float* __restrict__ bkv,
             float* __restrict__ keys, float* __restrict__ vals,
             float* __restrict__ sels)
{
    extern __shared__ char smem[];
    const uint32_t sb = s2u(smem);

    const int a = blockIdx.z;
    const int tid = threadIdx.x;
    const int lane = tid & 31;
    const int wid = tid >> 5;
    const int wm = wid & 3;
    const int wn = wid >> 2;
    const int lr = lane >> 2;
    const int lc = lane & 3;
    const int rowBase = blockIdx.y * 128;

    const bool kvJob = (blockIdx.x < 4);
    const int colBase = (kvJob ? blockIdx.x : (blockIdx.x - 4)) * 128;
    const int astride = kvJob ? NH : KP_C;
    const __half* pAh = (kvJob ? sah : cih) + (long)a * NB * astride + (long)rowBase * astride;
    const __half* pAl = (kvJob ? sal : cil) + (long)a * NB * astride + (long)rowBase * astride;
    const __half* pBh = (kvJob ? wKVh : wQh) + (long)colBase * KP_H;
    const __half* pBl = (kvJob ? wKVl : wQl) + (long)colBase * KP_H;

    float acc[2][8][4];
#pragma unroll
    for (int mt = 0; mt < 2; mt++)
#pragma unroll
        for (int nt = 0; nt < 8; nt++)
#pragma unroll
            for (int j = 0; j < 4; j++) acc[mt][nt][j] = 0.f;

    const int rrow = tid >> 2;
    const int grp  = tid & 3;

    auto issueStage = [&](int buf, int kc) {
#pragma unroll
        for (int t = 0; t < 2; t++) {
            const int row = rrow + t * 64;
            const uint32_t dst = (uint32_t)(row * (TS * 2) + grp * 16);
            const long aoff = (long)row * astride + kc + grp * 8;
            const long boff = (long)row * KP_H   + kc + grp * 8;
            CPA16(sb + OFF_AH + buf * BUFB + dst, pAh + aoff);
            CPA16(sb + OFF_AL + buf * BUFB + dst, pAl + aoff);
            CPA16(sb + OFF_BH + buf * BUFB + dst, pBh + boff);
            CPA16(sb + OFF_BL + buf * BUFB + dst, pBl + boff);
        }
    };

    const uint32_t aOff = (uint32_t)(((wm * 32 + (lane & 15)) * TS + (lane >> 4) * 8) * 2);
    const uint32_t bOff = (uint32_t)(((wn * 64 + (lane & 7) + ((lane >= 16) ? 8 : 0)) * TS
                                     + ((lane >> 3) & 1) * 8) * 2);

    const int nst = KP_H >> 5;   // 8
    issueStage(0, 0); CPC();

    for (int c = 0; c < nst; c++) {
        const int buf = c & 1;
        CPW0();
        __syncthreads();
        if (c + 1 < nst) { issueStage(buf ^ 1, (c + 1) * 32); CPC(); }

        const uint32_t sAh = sb + OFF_AH + buf * BUFB;
        const uint32_t sAl = sb + OFF_AL + buf * BUFB;
        const uint32_t sBh = sb + OFF_BH + buf * BUFB;
        const uint32_t sBl = sb + OFF_BL + buf * BUFB;

#pragma unroll
        for (int kk = 0; kk < 2; kk++) {
            const uint32_t kbB = kk * 32;
            uint32_t ah[2][4], al[2][4];
#pragma unroll
            for (int mt = 0; mt < 2; mt++) {
                const uint32_t ao = aOff + (uint32_t)(mt * 16 * TS * 2) + kbB;
                LDSM4(ah[mt][0], ah[mt][1], ah[mt][2], ah[mt][3], sAh + ao);
                LDSM4(al[mt][0], al[mt][1], al[mt][2], al[mt][3], sAl + ao);
            }
#pragma unroll
            for (int p = 0; p < 4; p++) {
                const uint32_t bo = bOff + (uint32_t)(p * 16 * TS * 2) + kbB;
                uint32_t bh[4], bl[4];
                LDSM4(bh[0], bh[1], bh[2], bh[3], sBh + bo);
                LDSM4(bl[0], bl[1], bl[2], bl[3], sBl + bo);
#pragma unroll
                for (int mt = 0; mt < 2; mt++) {
                    MMA_F16(acc[mt][2 * p],     ah[mt], bh[0], bh[1]);
                    MMA_F16(acc[mt][2 * p],     al[mt], bh[0], bh[1]);
                    MMA_F16(acc[mt][2 * p],     ah[mt], bl[0], bl[1]);
                    MMA_F16(acc[mt][2 * p + 1], ah[mt], bh[2], bh[3]);
                    MMA_F16(acc[mt][2 * p + 1], al[mt], bh[2], bh[3]);
                    MMA_F16(acc[mt][2 * p + 1], ah[mt], bl[2], bl[3]);
                }
            }
        }
    }

    // epilogue
#pragma unroll
    for (int mt = 0; mt < 2; mt++) {
        const int row = rowBase + wm * 32 + mt * 16 + lr;
#pragma unroll
        for (int nt = 0; nt < 8; nt++) {
            const int gcol = colBase + wn * 64 + nt * 8 + lc * 2;
            float b0 = 0.f, b1 = 0.f;
            if (kvJob) { b0 = bkv[gcol]; b1 = bkv[gcol + 1]; }
            float v0 = acc[mt][nt][0] + b0;
            float v1 = acc[mt][nt][1] + b1;
            float v2 = acc[mt][nt][2] + b0;
            float v3 = acc[mt][nt][3] + b1;
            if (kvJob && gcol >= 256) {
                v0 = v0 > 0.f ? v0 : 0.01f * v0;
                v1 = v1 > 0.f ? v1 : 0.01f * v1;
                v2 = v2 > 0.f ? v2 : 0.01f * v2;
                v3 = v3 > 0.f ? v3 : 0.01f * v3;
            }
            float* Yo = kvJob ? ((gcol >= 256) ? vals : keys) : sels;
            const int oc = gcol & 255;
            float2 o0 = {v0, v1};
            float2 o1 = {v2, v3};
            *(float2*)(Yo + ((long)a * NB + row) * NH + oc)     = o0;
            *(float2*)(Yo + ((long)a * NB + row + 8) * NH + oc) = o1;
        }
    }
}

// ---------------- critic GEMM (K=512, per-agent weights, fp32 out) -----------
__global__ __launch_bounds__(256, 2)
void gemmC(const __half* __restrict__ Ah, const __half* __restrict__ Al,
           const __half* __restrict__ Bh, const __half* __restrict__ Bl,
           const float* __restrict__ bias, float* __restrict__ Yf)
{
    extern __shared__ char smem[];
    const uint32_t sb = s2u(smem);

    const int a = blockIdx.z;
    const int tid = threadIdx.x;
    const int lane = tid & 31;
    const int wid = tid >> 5;
    const int wm = wid & 3;
    const int wn = wid >> 2;
    const int lr = lane >> 2;
    const int lc = lane & 3;
    const int rowBase = blockIdx.y * 128;
    const int colBase = blockIdx.x * 128;

    const __half* pAh = Ah + (long)a * NB * KP_C + (long)rowBase * KP_C;
    const __half* pAl = Al + (long)a * NB * KP_C + (long)rowBase * KP_C;
    const __half* pBh = Bh + (long)a * (256L * KP_C) + (long)colBase * KP_C;
    const __half* pBl = Bl + (long)a * (256L * KP_C) + (long)colBase * KP_C;

    float acc[2][8][4];
#pragma unroll
    for (int mt = 0; mt < 2; mt++)
#pragma unroll
        for (int nt = 0; nt < 8; nt++)
#pragma unroll
            for (int j = 0; j < 4; j++) acc[mt][nt][j] = 0.f;

    const int rrow = tid >> 2;
    const int grp  = tid & 3;

    auto issueStage = [&](int buf, int kc) {
#pragma unroll
        for (int t = 0; t < 2; t++) {
            const int row = rrow + t * 64;
            const uint32_t dst = (uint32_t)(row * (TS * 2) + grp * 16);
            const long off = (long)row * KP_C + kc + grp * 8;
            CPA16(sb + OFF_AH + buf * BUFB + dst, pAh + off);
            CPA16(sb + OFF_AL + buf * BUFB + dst, pAl + off);
            CPA16(sb + OFF_BH + buf * BUFB + dst, pBh + off);
            CPA16(sb + OFF_BL + buf * BUFB + dst, pBl + off);
        }
    };

    const uint32_t aOff = (uint32_t)(((wm * 32 + (lane & 15)) * TS + (lane >> 4) * 8) * 2);
    const uint32_t bOff = (uint32_t)(((wn * 64 + (lane & 7) + ((lane >= 16) ? 8 : 0)) * TS
                                     + ((lane >> 3) & 1) * 8) * 2);

    const int nst = KP_C >> 5;   // 16
    issueStage(0, 0); CPC();

    for (int c = 0; c < nst; c++) {
        const int buf = c & 1;
        CPW0();
        __syncthreads();
        if (c + 1 < nst) { issueStage(buf ^ 1, (c + 1) * 32); CPC(); }

        const uint32_t sAh = sb + OFF_AH + buf * BUFB;
        const uint32_t sAl = sb + OFF_AL + buf * BUFB;
        const uint32_t sBh = sb + OFF_BH + buf * BUFB;
        const uint32_t sBl = sb + OFF_BL + buf * BUFB;

#pragma unroll
        for (int kk = 0; kk < 2; kk++) {
            const uint32_t kbB = kk * 32;
            uint32_t ah[2][4], al[2][4];
#pragma unroll
            for (int mt = 0; mt < 2; mt++) {
                const uint32_t ao = aOff + (uint32_t)(mt * 16 * TS * 2) + kbB;
                LDSM4(ah[mt][0], ah[mt][1], ah[mt][2], ah[mt][3], sAh + ao);
                LDSM4(al[mt][0], al[mt][1], al[mt][2], al[mt][3], sAl + ao);
            }
#pragma unroll
            for (int p = 0; p < 4; p++) {
                const uint32_t bo = bOff + (uint32_t)(p * 16 * TS * 2) + kbB;
                uint32_t bh[4], bl[4];
                LDSM4(bh[0], bh[1], bh[2], bh[3], sBh + bo);
                LDSM4(bl[0], bl[1], bl[2], bl[3], sBl + bo);
#pragma unroll
                for (int mt = 0; mt < 2; mt++) {
                    MMA_F16(acc[mt][2 * p],     ah[mt], bh[0], bh[1]);
                    MMA_F16(acc[mt][2 * p],     al[mt], bh[0], bh[1]);
                    MMA_F16(acc[mt][2 * p],     ah[mt], bl[0], bl[1]);
                    MMA_F16(acc[mt][2 * p + 1], ah[mt], bh[2], bh[3]);
                    MMA_F16(acc[mt][2 * p + 1], al[mt], bh[2], bh[3]);
                    MMA_F16(acc[mt][2 * p + 1], ah[mt], bl[2], bl[3]);
                }
            }
        }
    }

#pragma unroll
    for (int mt = 0; mt < 2; mt++) {
        const int row = rowBase + wm * 32 + mt * 16 + lr;
#pragma unroll
        for (int nt = 0; nt < 8; nt++) {
            const int gcol = colBase + wn * 64 + nt * 8 + lc * 2;
            float b0 = bias[(long)a * NH + gcol];
            float b1 = bias[(long)a * NH + gcol + 1];
            float v0 = acc[mt][nt][0] + b0;
            float v1 = acc[mt][nt][1] + b1;
            float v2 = acc[mt][nt][2] + b0;
            float v3 = acc[mt][nt][3] + b1;
            v0 = v0 > 0.f ? v0 : 0.01f * v0;
            v1 = v1 > 0.f ? v1 : 0.01f * v1;
            v2 = v2 > 0.f ? v2 : 0.01f * v2;
            v3 = v3 > 0.f ? v3 : 0.01f * v3;
            float2 o0 = {v0, v1};
            float2 o1 = {v2, v3};
            *(float2*)(Yf + ((long)a * NB + row) * NH + gcol)     = o0;
            *(float2*)(Yf + ((long)a * NB + row + 8) * NH + gcol) = o1;
        }
    }
}

// ---------------- attention over agents (optimized) --------------------------
__global__ __launch_bounds__(256)
void attn_k(const float* __restrict__ keys, const float* __restrict__ sels,
            const float* __restrict__ vals,
            __half* __restrict__ ci_h, __half* __restrict__ ci_l)
{
    const int b = blockIdx.x;
    __shared__ float sk[NA][NH + 4];
    __shared__ float ss[NA][NH + 4];
    __shared__ float sv[NA][NH + 4];
    __shared__ float lg[NE][NA][NA];
    __shared__ float pr[NE][NA][NA];

    const int tid = threadIdx.x;
    for (int i = tid; i < NA * (NH / 4); i += 256) {
        int ag = i >> 6;
        int h4 = (i & 63) * 4;
        long off = ((long)ag * NB + b) * NH + h4;
        *(float4*)&sk[ag][h4] = *(const float4*)(keys + off);
        *(float4*)&ss[ag][h4] = *(const float4*)(sels + off);
        *(float4*)&sv[ag][h4] = *(const float4*)(vals + off);
    }
    __syncthreads();

    // logits via float4 dot products (16 LDS.128 per operand)
    {
        int e = tid >> 6;
        int i = (tid >> 3) & 7;
        int j = tid & 7;
        const float4* sp = (const float4*)&ss[i][e * ND];
        const float4* kp = (const float4*)&sk[j][e * ND];
        float s = 0.f;
#pragma unroll
        for (int d = 0; d < ND / 4; d++) {
            float4 x = sp[d];
            float4 y = kp[d];
            s = fmaf(x.x, y.x, s);
            s = fmaf(x.y, y.y, s);
            s = fmaf(x.z, y.z, s);
            s = fmaf(x.w, y.w, s);
        }
        lg[e][i][j] = (i == j) ? -1e9f : s * 0.125f;
    }
    __syncthreads();

    if (tid < NE * NA) {
        int e = tid >> 3;
        int i = tid & 7;
        float mx = -1e30f;
#pragma unroll
        for (int j = 0; j < NA; j++) mx = fmaxf(mx, lg[e][i][j]);
        float p[NA]; float sum = 0.f;
#pragma unroll
        for (int j = 0; j < NA; j++) { p[j] = expf(lg[e][i][j] - mx); sum += p[j]; }
        float inv = 1.f / sum;
#pragma unroll
        for (int j = 0; j < NA; j++) pr[e][i][j] = p[j] * inv;
    }
    __syncthreads();

    // output: 2 adjacent h per thread -> __half2 stores
    for (int o = tid; o < NA * (NH / 2); o += 256) {
        int i  = o >> 7;            // agent
        int hh = (o & 127) << 1;    // even h
        int e  = hh >> 6;
        const float* pw = pr[e][i];
        const float* v0p = &sv[0][hh];
        float s0 = 0.f, s1 = 0.f;
#pragma unroll
        for (int j = 0; j < NA; j++) {
            float w = pw[j];
            s0 = fmaf(w, sv[j][hh],     s0);
            s1 = fmaf(w, sv[j][hh + 1], s1);
        }
        (void)v0p;
        __half h0, l0, h1, l1;
        split_h(s0, h0, l0);
        split_h(s1, h1, l1);
        long idx = ((long)i * NB + b) * KP_C + NH + hh;
        *(__half2*)(ci_h + idx) = __halves2half2(h0, h1);
        *(__half2*)(ci_l + idx) = __halves2half2(l0, l1);
    }
}

// ---------------- final: argmax(actions) + q -------------------------------
__global__ __launch_bounds__(256)
void q_k(const float* __restrict__ hbuf, const float* __restrict__ actions,
         const float* __restrict__ c_W2, const float* __restrict__ c_b2,
         float* __restrict__ q)
{
    const int gw = (blockIdx.x * blockDim.x + threadIdx.x) >> 5;
    const int lane = threadIdx.x & 31;
    if (gw >= NA * NB) return;
    const int a = gw >> 14;
    const int b = gw & (NB - 1);

    const float* ap = actions + ((long)a * NB + b) * NACT;
    float av = (lane < NACT) ? ap[lane] : -1e30f;
    int ai = lane;
#pragma unroll
    for (int off = 16; off > 0; off >>= 1) {
        float ov = __shfl_down_sync(0xFFFFFFFFu, av, off);
        int   oi = __shfl_down_sync(0xFFFFFFFFu, ai, off);
        if (ov > av || (ov == av && oi < ai)) { av = ov; ai = oi; }
    }
    ai = __shfl_sync(0xFFFFFFFFu, ai, 0);

    const float* hp = hbuf + ((long)a * NB + b) * NH;
    const float* wp = c_W2 + (long)a * NH * NACT + ai;
    float s = 0.f;
#pragma unroll
    for (int it = 0; it < NH / 32; it++) {
        int h = lane + it * 32;
        s = fmaf(hp[h], wp[(long)h * NACT], s);
    }
#pragma unroll
    for (int off = 16; off > 0; off >>= 1)
        s += __shfl_down_sync(0xFFFFFFFFu, s, off);
    if (lane == 0) q[gw] = s + c_b2[a * NACT + ai];
}

// ---------------- launcher --------------------------------------------------
extern "C" void kernel_launch(void* const* d_in, const int* in_sizes, int n_in,
                              void* d_out, int out_size)
{
    const float* states  = (const float*)d_in[0];
    const float* actions = (const float*)d_in[1];
    const float* enc_W   = (const float*)d_in[2];
    const float* enc_b   = (const float*)d_in[3];
    const float* s_W     = (const float*)d_in[4];
    const float* s_b     = (const float*)d_in[5];
    const float* key_W   = (const float*)d_in[6];
    const float* sel_W   = (const float*)d_in[7];
    const float* val_W   = (const float*)d_in[8];
    const float* val_b   = (const float*)d_in[9];
    const float* c_W1    = (const float*)d_in[10];
    const float* c_b1    = (const float*)d_in[11];
    const float* c_W2    = (const float*)d_in[12];
    const float* c_b2    = (const float*)d_in[13];
    float* q = (float*)d_out;

    __half *sah, *sal, *cih, *cil;
    cudaGetSymbolAddress((void**)&sah, g_sa_h);
    cudaGetSymbolAddress((void**)&sal, g_sa_l);
    cudaGetSymbolAddress((void**)&cih, g_ci_h);
    cudaGetSymbolAddress((void**)&cil, g_ci_l);
    float *keys, *vals, *sels, *hbuf, *bkv, *bes;
    cudaGetSymbolAddress((void**)&keys, g_keys);
    cudaGetSymbolAddress((void**)&vals, g_vals);
    cudaGetSymbolAddress((void**)&sels, g_sels);
    cudaGetSymbolAddress((void**)&hbuf, g_h);
    cudaGetSymbolAddress((void**)&bkv,  g_bias_kv);
    cudaGetSymbolAddress((void**)&bes,  g_bias_es);
    __half *wESh, *wESl, *wCh, *wCl, *wKVh, *wKVl, *wQh, *wQl;
    cudaGetSymbolAddress((void**)&wESh, g_wES_h);
    cudaGetSymbolAddress((void**)&wESl, g_wES_l);
    cudaGetSymbolAddress((void**)&wCh, g_wC_h);
    cudaGetSymbolAddress((void**)&wCl, g_wC_l);
    cudaGetSymbolAddress((void**)&wKVh, g_wKV_h);
    cudaGetSymbolAddress((void**)&wKVl, g_wKV_l);
    cudaGetSymbolAddress((void**)&wQh, g_wQ_h);
    cudaGetSymbolAddress((void**)&wQl, g_wQ_l);

    cudaFuncSetAttribute(gemmES,  cudaFuncAttributeMaxDynamicSharedMemorySize, SMEM_TOT);
    cudaFuncSetAttribute(gemmKVQ, cudaFuncAttributeMaxDynamicSharedMemorySize, SMEM_TOT);
    cudaFuncSetAttribute(gemmC,   cudaFuncAttributeMaxDynamicSharedMemorySize, SMEM_TOT);

    // ---- prep: 1 launch -----------------------------------------------------
    prep_all<<<(unsigned)((SEG_END + 255) / 256), 256>>>(
        enc_W, s_W, c_W1, key_W, val_W, sel_W, val_b, enc_b, s_b,
        wESh, wESl, wCh, wCl, wKVh, wKVl, wQh, wQl, bkv, bes);

    dim3 blk(256);

    // 1) fused sa_enc + s_enc (direct fp32 A)
    gemmES<<<dim3(4, NB / 128, NA), blk, SMEM_TOT>>>(
        states, actions, wESh, wESl, bes, sah, sal, cih, cil);

    // 2) merged keys|vals (N=512) + sels (N=256) in one launch
    gemmKVQ<<<dim3(6, NB / 128, NA), blk, SMEM_TOT>>>(
        sah, sal, cih, cil, wKVh, wKVl, wQh, wQl, bkv, keys, vals, sels);

    // 3) attention -> ci cols [256,512)
    attn_k<<<NB, 256>>>(keys, sels, vals, cih, cil);

    // 4) h = lrelu(ci @ c_W1 + c_b1)
    gemmC<<<dim3(2, NB / 128, NA), blk, SMEM_TOT>>>(cih, cil, wCh, wCl, c_b1, hbuf);

    // 5) q
    q_k<<<(NA * NB * 32) / 256, 256>>>(hbuf, actions, c_W2, c_b2, q);
}